// round 1
// baseline (speedup 1.0000x reference)
#include <cuda_runtime.h>
#include <math.h>

#define BATCH 4
#define SEQ   4096
#define EMB   512
#define HD    64
#define BS    (BATCH*SEQ)      // 16384 rows
#define MTILE 128
#define NMT   (SEQ/MTILE)      // 32
#define NSPLIT 8
#define KTILE 32

// scratch (static __device__ allocation is allowed; cudaMalloc is not)
__device__ float g_Q[BS*HD];
__device__ float g_K[BS*HD];
__device__ float g_V[BS*HD];
__device__ float g_Op[NSPLIT][BS*HD];   // unnormalized partial outputs
__device__ float g_Mx[NSPLIT][BS];      // running max per split
__device__ float g_L [NSPLIT][BS];      // running sumexp per split

// ---------------- QKV projection: out = x @ W, M=16384 K=512 N=64 ----------------
__global__ __launch_bounds__(256) void qkv_kernel(const float* __restrict__ x,
                                                  const float* __restrict__ WQ,
                                                  const float* __restrict__ WK,
                                                  const float* __restrict__ WV) {
    const float* W = (blockIdx.y == 0) ? WQ : (blockIdx.y == 1 ? WK : WV);
    float* out     = (blockIdx.y == 0) ? g_Q : (blockIdx.y == 1 ? g_K : g_V);

    __shared__ float xs[128][33];   // +1 pad: column reads conflict-free
    __shared__ float ws[32][64];

    int tid  = threadIdx.x;
    int trow = tid >> 4;     // 0..15 -> rows trow*8..+7
    int tcol = tid & 15;     // 0..15 -> cols tcol*4..+3
    long row0 = (long)blockIdx.x * 128;

    float acc[8][4];
    #pragma unroll
    for (int i = 0; i < 8; i++)
        #pragma unroll
        for (int j = 0; j < 4; j++) acc[i][j] = 0.f;

    for (int k0 = 0; k0 < EMB; k0 += 32) {
        #pragma unroll
        for (int i = 0; i < 4; i++) {           // x tile: 128x32 = 1024 float4
            int id = tid + i * 256;
            int r = id >> 3, c4 = id & 7;
            float4 v = *(const float4*)&x[(row0 + r) * EMB + k0 + c4 * 4];
            xs[r][c4*4+0] = v.x; xs[r][c4*4+1] = v.y;
            xs[r][c4*4+2] = v.z; xs[r][c4*4+3] = v.w;
        }
        #pragma unroll
        for (int i = 0; i < 2; i++) {           // W tile: 32x64 = 512 float4
            int id = tid + i * 256;
            int r = id >> 4, c4 = id & 15;
            *(float4*)&ws[r][c4*4] = *(const float4*)&W[(k0 + r) * HD + c4 * 4];
        }
        __syncthreads();

        #pragma unroll
        for (int k = 0; k < 32; k++) {
            float wr[4];
            #pragma unroll
            for (int j = 0; j < 4; j++) wr[j] = ws[k][tcol*4 + j];
            #pragma unroll
            for (int i = 0; i < 8; i++) {
                float xv = xs[trow*8 + i][k];
                #pragma unroll
                for (int j = 0; j < 4; j++) acc[i][j] = fmaf(xv, wr[j], acc[i][j]);
            }
        }
        __syncthreads();
    }

    #pragma unroll
    for (int i = 0; i < 8; i++)
        #pragma unroll
        for (int j = 0; j < 4; j++)
            out[(row0 + trow*8 + i) * HD + tcol*4 + j] = acc[i][j];
}

// ---------------- Flash attention, causal, key-split for balance ----------------
// Block: 256 threads; thread = (query row r = tid/2, half = tid&1 owning 32 of 64 dims).
// grid = (NSPLIT, NMT, BATCH)
__global__ __launch_bounds__(256, 2) void attn_kernel() {
    const int split = blockIdx.x;
    const int m     = blockIdx.y;
    const int b     = blockIdx.z;
    const int tid   = threadIdx.x;
    const int r     = tid >> 1;
    const int half  = tid & 1;
    const int q_global = m * MTILE + r;
    const long qrow = (long)b * SEQ + q_global;
    const float scale = 0.044194173824159216f;   // 1/sqrt(512)

    float q[32];
    #pragma unroll
    for (int d = 0; d < 32; d += 4) {
        float4 v = *(const float4*)&g_Q[qrow * HD + half*32 + d];
        q[d] = v.x; q[d+1] = v.y; q[d+2] = v.z; q[d+3] = v.w;
    }

    const int nk    = (m + 1) * MTILE;
    const int chunk = nk / NSPLIT;            // (m+1)*16, >= 16
    const int kbeg  = split * chunk;
    const int kend  = kbeg + chunk;

    __shared__ float Ks[KTILE][HD];
    __shared__ float Vs[KTILE][HD];

    float o[32];
    #pragma unroll
    for (int d = 0; d < 32; d++) o[d] = 0.f;
    float mrun = -INFINITY, lrun = 0.f;

    for (int kt = kbeg; kt < kend; kt += KTILE) {
        #pragma unroll
        for (int i = 0; i < 2; i++) {         // load 32x64 K and V tiles (512 float4 each)
            int id = tid + i * 256;
            int rr = id >> 4, c4 = id & 15;
            int kk = kt + rr;
            float4 vk = make_float4(0.f, 0.f, 0.f, 0.f);
            float4 vv = make_float4(0.f, 0.f, 0.f, 0.f);
            if (kk < kend) {
                vk = *(const float4*)&g_K[((long)b*SEQ + kk) * HD + c4*4];
                vv = *(const float4*)&g_V[((long)b*SEQ + kk) * HD + c4*4];
            }
            *(float4*)&Ks[rr][c4*4] = vk;
            *(float4*)&Vs[rr][c4*4] = vv;
        }
        __syncthreads();

        #pragma unroll
        for (int sub = 0; sub < 2; sub++) {   // 16-key sub-tiles keep regs <=128
            float s[16];
            #pragma unroll
            for (int jj = 0; jj < 16; jj++) {
                int j = sub * 16 + jj;
                float p = 0.f;
                #pragma unroll
                for (int d4 = 0; d4 < 8; d4++) {
                    float4 kv = *(const float4*)&Ks[j][half*32 + d4*4];
                    p = fmaf(q[d4*4+0], kv.x, p);
                    p = fmaf(q[d4*4+1], kv.y, p);
                    p = fmaf(q[d4*4+2], kv.z, p);
                    p = fmaf(q[d4*4+3], kv.w, p);
                }
                p += __shfl_xor_sync(0xffffffffu, p, 1);   // combine D-halves
                int kk = kt + j;
                s[jj] = (kk <= q_global && kk < kend) ? p * scale : -INFINITY;
            }
            float tmax = -INFINITY;
            #pragma unroll
            for (int jj = 0; jj < 16; jj++) tmax = fmaxf(tmax, s[jj]);

            if (tmax != -INFINITY) {
                float mnew = fmaxf(mrun, tmax);
                float corr = __expf(mrun - mnew);   // exp(-inf)=0 on first hit
                lrun *= corr;
                #pragma unroll
                for (int d = 0; d < 32; d++) o[d] *= corr;
                #pragma unroll
                for (int jj = 0; jj < 16; jj++) {
                    float p = __expf(s[jj] - mnew);
                    lrun += p;
                    int j = sub * 16 + jj;
                    #pragma unroll
                    for (int d4 = 0; d4 < 8; d4++) {
                        float4 vv = *(const float4*)&Vs[j][half*32 + d4*4];
                        o[d4*4+0] = fmaf(p, vv.x, o[d4*4+0]);
                        o[d4*4+1] = fmaf(p, vv.y, o[d4*4+1]);
                        o[d4*4+2] = fmaf(p, vv.z, o[d4*4+2]);
                        o[d4*4+3] = fmaf(p, vv.w, o[d4*4+3]);
                    }
                }
                mrun = mnew;
            }
        }
        __syncthreads();
    }

    #pragma unroll
    for (int d = 0; d < 32; d += 4)
        *(float4*)&g_Op[split][qrow * HD + half*32 + d] =
            make_float4(o[d], o[d+1], o[d+2], o[d+3]);
    if (half == 0) { g_Mx[split][qrow] = mrun; g_L[split][qrow] = lrun; }
}

// ---------------- merge split partials ----------------
__global__ void combine_kernel(float* __restrict__ out) {
    int idx = blockIdx.x * blockDim.x + threadIdx.x;
    if (idx >= BS * HD) return;
    int row = idx >> 6;

    float M = -INFINITY;
    #pragma unroll
    for (int i = 0; i < NSPLIT; i++) M = fmaxf(M, g_Mx[i][row]);

    float Lt = 0.f, acc = 0.f;
    #pragma unroll
    for (int i = 0; i < NSPLIT; i++) {
        float w = __expf(g_Mx[i][row] - M);   // empty split: exp(-inf)=0
        Lt  = fmaf(g_L[i][row], w, Lt);
        acc = fmaf(g_Op[i][idx], w, acc);
    }
    out[idx] = acc / Lt;
}

extern "C" void kernel_launch(void* const* d_in, const int* in_sizes, int n_in,
                              void* d_out, int out_size) {
    const float* x  = (const float*)d_in[0];
    const float* WQ = (const float*)d_in[1];
    const float* WK = (const float*)d_in[2];
    const float* WV = (const float*)d_in[3];
    float* out = (float*)d_out;

    qkv_kernel<<<dim3(BS / 128, 3), 256>>>(x, WQ, WK, WV);
    attn_kernel<<<dim3(NSPLIT, NMT, BATCH), 256>>>();
    combine_kernel<<<(BS * HD + 255) / 256, 256>>>(out);
}

// round 4
// speedup vs baseline: 3.7201x; 3.7201x over previous
#include <cuda_runtime.h>
#include <cuda_bf16.h>
#include <math.h>
#include <stdint.h>

#define BATCH 4
#define SEQ   4096
#define EMB   512
#define HD    64
#define BS    (BATCH*SEQ)
#define MT    128
#define NMT   (SEQ/MT)            // 32
#define KT    128
#define TPB   8                   // max key tiles per block
#define BLKS_PER_B 80             // sum_m ceil((m+1)/8)
#define MAXSPLIT 4
#define SCALE_LOG2E 0.06375872036f   // log2(e)/sqrt(512)

// ---------------- device scratch ----------------
__device__ unsigned g_Qhi[BS*32], g_Qlo[BS*32];     // packed bf16 pairs, [row][32 words]
__device__ unsigned g_Khi[BS*32], g_Klo[BS*32];
__device__ float    g_Vf[BS*64];
__device__ unsigned g_Vthi[BATCH*64*2048];          // V^T packed key-pairs, [b*64+d][2048]
__device__ unsigned g_Vtlo[BATCH*64*2048];
__device__ float    g_Opart[(size_t)BATCH*NMT*MAXSPLIT*MT*HD];
__device__ float    g_Lpart[BATCH*NMT*MAXSPLIT*MT];

// pack two fp32 -> bf16x2 (upper = o (odd), lower = e (even))
static __device__ __forceinline__ unsigned packbf(float o, float e) {
    unsigned r;
    asm("cvt.rn.bf16x2.f32 %0, %1, %2;" : "=r"(r) : "f"(o), "f"(e));
    return r;
}

#define MMA4(C, A, b0v, b1v)                                                     \
    asm volatile("mma.sync.aligned.m16n8k16.row.col.f32.bf16.bf16.f32 "          \
        "{%0,%1,%2,%3}, {%4,%5,%6,%7}, {%8,%9}, {%0,%1,%2,%3};"                  \
        : "+f"((C)[0]), "+f"((C)[1]), "+f"((C)[2]), "+f"((C)[3])                 \
        : "r"((A)[0]), "r"((A)[1]), "r"((A)[2]), "r"((A)[3]), "r"(b0v), "r"(b1v))

// ---------------- QKV projection (fp32 math; Q,K -> bf16 hi/lo packed; V -> fp32) -----
__global__ __launch_bounds__(256) void qkv_kernel(const float* __restrict__ x,
                                                  const float* __restrict__ WQ,
                                                  const float* __restrict__ WK,
                                                  const float* __restrict__ WV) {
    const float* W = (blockIdx.y == 0) ? WQ : (blockIdx.y == 1 ? WK : WV);

    __shared__ float xs[128][33];
    __shared__ float ws[32][64];

    int tid  = threadIdx.x;
    int trow = tid >> 4;
    int tcol = tid & 15;
    long row0 = (long)blockIdx.x * 128;

    float acc[8][4];
    #pragma unroll
    for (int i = 0; i < 8; i++)
        #pragma unroll
        for (int j = 0; j < 4; j++) acc[i][j] = 0.f;

    for (int k0 = 0; k0 < EMB; k0 += 32) {
        #pragma unroll
        for (int i = 0; i < 4; i++) {
            int id = tid + i * 256;
            int r = id >> 3, c4 = id & 7;
            float4 v = *(const float4*)&x[(row0 + r) * EMB + k0 + c4 * 4];
            xs[r][c4*4+0] = v.x; xs[r][c4*4+1] = v.y;
            xs[r][c4*4+2] = v.z; xs[r][c4*4+3] = v.w;
        }
        #pragma unroll
        for (int i = 0; i < 2; i++) {
            int id = tid + i * 256;
            int r = id >> 4, c4 = id & 15;
            *(float4*)&ws[r][c4*4] = *(const float4*)&W[(k0 + r) * HD + c4 * 4];
        }
        __syncthreads();
        #pragma unroll
        for (int k = 0; k < 32; k++) {
            float wr[4];
            #pragma unroll
            for (int j = 0; j < 4; j++) wr[j] = ws[k][tcol*4 + j];
            #pragma unroll
            for (int i = 0; i < 8; i++) {
                float xv = xs[trow*8 + i][k];
                #pragma unroll
                for (int j = 0; j < 4; j++) acc[i][j] = fmaf(xv, wr[j], acc[i][j]);
            }
        }
        __syncthreads();
    }

    if (blockIdx.y == 2) {   // V: fp32 out
        #pragma unroll
        for (int i = 0; i < 8; i++) {
            long row = row0 + trow*8 + i;
            *(float4*)&g_Vf[row*64 + tcol*4] =
                make_float4(acc[i][0], acc[i][1], acc[i][2], acc[i][3]);
        }
    } else {                 // Q or K: bf16 hi/lo packed words
        unsigned* oh = (blockIdx.y == 0) ? g_Qhi : g_Khi;
        unsigned* ol = (blockIdx.y == 0) ? g_Qlo : g_Klo;
        #pragma unroll
        for (int i = 0; i < 8; i++) {
            long row = row0 + trow*8 + i;
            #pragma unroll
            for (int j = 0; j < 4; j += 2) {
                float v0 = acc[i][j], v1 = acc[i][j+1];
                unsigned hw = packbf(v1, v0);
                float h0 = __uint_as_float(hw << 16);
                float h1 = __uint_as_float(hw & 0xffff0000u);
                unsigned lw = packbf(v1 - h1, v0 - h0);
                long wi = row * 32 + tcol*2 + (j >> 1);
                oh[wi] = hw;
                ol[wi] = lw;
            }
        }
    }
}

// ---------------- V transpose: fp32 [row][64] -> packed bf16 hi/lo [b*64+d][keypair] ---
__global__ __launch_bounds__(256) void vtrans_kernel() {
    __shared__ float ts[64][65];
    long r0 = (long)blockIdx.x * 64;
    int b  = (int)(r0 >> 12);
    int k0 = (int)(r0 & 4095);

    #pragma unroll
    for (int i = 0; i < 16; i++) {
        int idx = threadIdx.x + i * 256;
        int r = idx >> 6, c = idx & 63;
        ts[r][c] = g_Vf[(r0 + r) * 64 + c];
    }
    __syncthreads();

    int kp = threadIdx.x & 31;
    int d0 = (threadIdx.x >> 5) * 8;
    #pragma unroll
    for (int i = 0; i < 8; i++) {
        int d = d0 + i;
        float v0 = ts[2*kp][d], v1 = ts[2*kp+1][d];   // even, odd key
        unsigned hw = packbf(v1, v0);
        float h0 = __uint_as_float(hw << 16);
        float h1 = __uint_as_float(hw & 0xffff0000u);
        unsigned lw = packbf(v1 - h1, v0 - h0);
        size_t wi = ((size_t)(b * 64 + d)) * 2048 + (k0 >> 1) + kp;
        g_Vthi[wi] = hw;
        g_Vtlo[wi] = lw;
    }
}

// ---------------- HMMA flash attention (no online max), key-split ----------------
// smem: Khi[128][36]w, Klo[128][36]w, Vthi[64][68]w, Vtlo[64][68]w  (words)
#define S_KHI 0
#define S_KLO 18432
#define S_VHI 36864
#define S_VLO 54272
#define SMEM_BYTES 71680

__global__ __launch_bounds__(256, 1) void attn_mma() {
    extern __shared__ char smem[];
    unsigned* Khs = (unsigned*)(smem + S_KHI);
    unsigned* Kls = (unsigned*)(smem + S_KLO);
    unsigned* Vhs = (unsigned*)(smem + S_VHI);
    unsigned* Vls = (unsigned*)(smem + S_VLO);

    const int tid  = threadIdx.x;
    const int w    = tid >> 5;
    const int lane = tid & 31;
    const int g    = lane >> 2;
    const int t4   = lane & 3;

    // decode (m, split)
    int rid = blockIdx.x, m = 0, split = 0;
    #pragma unroll 1
    for (int mm = 0; mm < NMT; mm++) {
        int c = (mm + TPB) >> 3;
        if (rid < c) { m = mm; split = rid; break; }
        rid -= c;
    }
    const int b   = blockIdx.y;
    const int kt0 = split * TPB;
    const int kt1 = (kt0 + TPB < m + 1) ? (kt0 + TPB) : (m + 1);
    const long brow = (long)b * SEQ;
    const int rg = m * MT + w * 16 + g;    // global q row (low of pair)

    // Q fragments (persist across tiles)
    unsigned qh[4][4], ql[4][4];
    {
        long base0 = (brow + rg) * 32;
        long base8 = base0 + 8 * 32;
        #pragma unroll
        for (int kk = 0; kk < 4; kk++) {
            int wlo = 8*kk + t4, whi = wlo + 4;
            qh[kk][0] = g_Qhi[base0 + wlo]; qh[kk][1] = g_Qhi[base8 + wlo];
            qh[kk][2] = g_Qhi[base0 + whi]; qh[kk][3] = g_Qhi[base8 + whi];
            ql[kk][0] = g_Qlo[base0 + wlo]; ql[kk][1] = g_Qlo[base8 + wlo];
            ql[kk][2] = g_Qlo[base0 + whi]; ql[kk][3] = g_Qlo[base8 + whi];
        }
    }

    float O[8][4];
    #pragma unroll
    for (int i = 0; i < 8; i++)
        #pragma unroll
        for (int j = 0; j < 4; j++) O[i][j] = 0.f;
    float lacc0 = 0.f, lacc1 = 0.f;

    for (int kt = kt0; kt < kt1; kt++) {
        // ---- load K hi/lo (128 rows x 32 words) into smem ----
        {
            const uint4* KH = (const uint4*)g_Khi + (brow + (long)kt * KT) * 8;
            const uint4* KL = (const uint4*)g_Klo + (brow + (long)kt * KT) * 8;
            #pragma unroll
            for (int i = 0; i < 4; i++) {
                int idx = tid + i * 256;
                int r = idx >> 3, c4 = idx & 7;
                *(uint4*)(Khs + r*36 + c4*4) = KH[r*8 + c4];
                *(uint4*)(Kls + r*36 + c4*4) = KL[r*8 + c4];
            }
            // ---- Vt hi/lo: 64 rows x 64 words = 1024 uint4 each ----
            #pragma unroll
            for (int i = 0; i < 4; i++) {
                int idx = tid + i * 256;
                int d = idx >> 4, c4 = idx & 15;
                size_t vbase = ((size_t)(b*64 + d)) * 512 + (size_t)kt * 16 + c4;
                *(uint4*)(Vhs + d*68 + c4*4) = ((const uint4*)g_Vthi)[vbase];
                *(uint4*)(Vls + d*68 + c4*4) = ((const uint4*)g_Vtlo)[vbase];
            }
        }
        __syncthreads();

        // ---- S = Qhi*Khi + Qhi*Klo + Qlo*Khi  (16 n-tiles of 8 keys) ----
        float S[16][4];
        #pragma unroll
        for (int j = 0; j < 16; j++)
            #pragma unroll
            for (int r = 0; r < 4; r++) S[j][r] = 0.f;

        #pragma unroll
        for (int kk = 0; kk < 4; kk++) {
            #pragma unroll
            for (int j = 0; j < 16; j++) {
                const unsigned* kh = Khs + (j*8 + g)*36 + 8*kk + t4;
                const unsigned* kl = Kls + (j*8 + g)*36 + 8*kk + t4;
                unsigned bh0 = kh[0], bh1 = kh[4];
                unsigned bl0 = kl[0], bl1 = kl[4];
                MMA4(S[j], qh[kk], bh0, bh1);
                MMA4(S[j], qh[kk], bl0, bl1);
                MMA4(S[j], ql[kk], bh0, bh1);
            }
        }

        // ---- softmax (no max-sub) + build P hi/lo A-fragments ----
        const int diag = (kt == m);
        const int kbase = kt * KT;
        unsigned ph[8][4], pl[8][4];
        #pragma unroll
        for (int j = 0; j < 16; j++) {
            float p0 = exp2f(S[j][0] * SCALE_LOG2E);
            float p1 = exp2f(S[j][1] * SCALE_LOG2E);
            float p2 = exp2f(S[j][2] * SCALE_LOG2E);
            float p3 = exp2f(S[j][3] * SCALE_LOG2E);
            if (diag) {
                int col = kbase + j*8 + 2*t4;
                if (col     > rg)     p0 = 0.f;
                if (col + 1 > rg)     p1 = 0.f;
                if (col     > rg + 8) p2 = 0.f;
                if (col + 1 > rg + 8) p3 = 0.f;
            }
            lacc0 += p0 + p1;
            lacc1 += p2 + p3;
            unsigned h01 = packbf(p1, p0);
            unsigned h23 = packbf(p3, p2);
            float r0 = p0 - __uint_as_float(h01 << 16);
            float r1 = p1 - __uint_as_float(h01 & 0xffff0000u);
            float r2 = p2 - __uint_as_float(h23 << 16);
            float r3 = p3 - __uint_as_float(h23 & 0xffff0000u);
            int kk2 = j >> 1, hf = (j & 1) * 2;
            ph[kk2][hf]     = h01;
            ph[kk2][hf + 1] = h23;
            pl[kk2][hf]     = packbf(r1, r0);
            pl[kk2][hf + 1] = packbf(r3, r2);
        }

        // ---- O += Phi*Vhi + Phi*Vlo + Plo*Vhi ----
        #pragma unroll
        for (int kk2 = 0; kk2 < 8; kk2++) {
            #pragma unroll
            for (int n2 = 0; n2 < 8; n2++) {
                const unsigned* vh = Vhs + (n2*8 + g)*68 + 8*kk2 + t4;
                const unsigned* vl = Vls + (n2*8 + g)*68 + 8*kk2 + t4;
                unsigned bh0 = vh[0], bh1 = vh[4];
                unsigned bl0 = vl[0], bl1 = vl[4];
                MMA4(O[n2], ph[kk2], bh0, bh1);
                MMA4(O[n2], ph[kk2], bl0, bl1);
                MMA4(O[n2], pl[kk2], bh0, bh1);
            }
        }
        __syncthreads();
    }

    // ---- reduce l over quad, write partials ----
    lacc0 += __shfl_xor_sync(0xffffffffu, lacc0, 1);
    lacc0 += __shfl_xor_sync(0xffffffffu, lacc0, 2);
    lacc1 += __shfl_xor_sync(0xffffffffu, lacc1, 1);
    lacc1 += __shfl_xor_sync(0xffffffffu, lacc1, 2);

    const int pidx = (b * NMT + m) * MAXSPLIT + split;
    if (t4 == 0) {
        g_Lpart[pidx*128 + w*16 + g]     = lacc0;
        g_Lpart[pidx*128 + w*16 + g + 8] = lacc1;
    }
    float* op = g_Opart + ((size_t)pidx*128 + w*16 + g) * 64;
    #pragma unroll
    for (int n2 = 0; n2 < 8; n2++) {
        *(float2*)&op[n2*8 + 2*t4]          = make_float2(O[n2][0], O[n2][1]);
        *(float2*)&op[8*64 + n2*8 + 2*t4]   = make_float2(O[n2][2], O[n2][3]);
    }
}

// ---------------- combine split partials ----------------
__global__ void combine_kernel(float* __restrict__ out) {
    int idx = blockIdx.x * blockDim.x + threadIdx.x;
    if (idx >= BS * HD) return;
    int row = idx >> 6, d = idx & 63;
    int b = row >> 12;
    int s_in_b = row & 4095;
    int m = s_in_b >> 7, r = s_in_b & 127;
    int nsp = (m + TPB) >> 3;
    int p0 = (b * NMT + m) * MAXSPLIT;

    float sO = 0.f, sL = 0.f;
    #pragma unroll 1
    for (int s = 0; s < nsp; s++) {
        int p = p0 + s;
        sO += g_Opart[((size_t)p * 128 + r) * 64 + d];
        sL += g_Lpart[p * 128 + r];
    }
    out[idx] = sO / sL;
}

extern "C" void kernel_launch(void* const* d_in, const int* in_sizes, int n_in,
                              void* d_out, int out_size) {
    const float* x  = (const float*)d_in[0];
    const float* WQ = (const float*)d_in[1];
    const float* WK = (const float*)d_in[2];
    const float* WV = (const float*)d_in[3];
    float* out = (float*)d_out;

    cudaFuncSetAttribute(attn_mma, cudaFuncAttributeMaxDynamicSharedMemorySize, SMEM_BYTES);

    qkv_kernel<<<dim3(BS / 128, 3), 256>>>(x, WQ, WK, WV);
    vtrans_kernel<<<BS / 64, 256>>>();
    attn_mma<<<dim3(BLKS_PER_B, BATCH), 256, SMEM_BYTES>>>();
    combine_kernel<<<(BS * HD + 255) / 256, 256>>>(out);
}

// round 6
// speedup vs baseline: 4.8670x; 1.3083x over previous
#include <cuda_runtime.h>
#include <cuda_bf16.h>
#include <math.h>
#include <stdint.h>

#define BATCH 4
#define SEQ   4096
#define EMB   512
#define HD    64
#define BS    (BATCH*SEQ)
#define MT    128
#define NMT   (SEQ/MT)            // 32
#define KT    128
#define TPB   8                   // max key tiles per block
#define BLKS_PER_B 80             // sum_m ceil((m+1)/8)
#define MAXSPLIT 4
#define SCALE_LOG2E 0.06375872036f   // log2(e)/sqrt(512)

// ---------------- device scratch ----------------
__device__ unsigned g_Qhi[BS*32], g_Qlo[BS*32];     // packed bf16 pairs, [row][32 words]
__device__ unsigned g_Khi[BS*32], g_Klo[BS*32];
__device__ unsigned g_Vthi[BATCH*64*2048];          // V^T packed key-pairs, [b*64+d][2048]
__device__ unsigned g_Vtlo[BATCH*64*2048];
__device__ unsigned g_Wthi[192*256], g_Wtlo[192*256]; // W^T packed: [n(Q64|K64|V64)][256 kw]
__device__ float    g_Opart[(size_t)BATCH*NMT*MAXSPLIT*MT*HD];
__device__ float    g_Lpart[BATCH*NMT*MAXSPLIT*MT];

// pack two fp32 -> bf16x2 (upper = o (odd), lower = e (even))
static __device__ __forceinline__ unsigned packbf(float o, float e) {
    unsigned r;
    asm("cvt.rn.bf16x2.f32 %0, %1, %2;" : "=r"(r) : "f"(o), "f"(e));
    return r;
}

#define MMA4(C, A, b0v, b1v)                                                     \
    asm volatile("mma.sync.aligned.m16n8k16.row.col.f32.bf16.bf16.f32 "          \
        "{%0,%1,%2,%3}, {%4,%5,%6,%7}, {%8,%9}, {%0,%1,%2,%3};"                  \
        : "+f"((C)[0]), "+f"((C)[1]), "+f"((C)[2]), "+f"((C)[3])                 \
        : "r"((A)[0]), "r"((A)[1]), "r"((A)[2]), "r"((A)[3]), "r"(b0v), "r"(b1v))

// ---------------- W^T prep: [n=192][k=512] -> packed bf16 hi/lo [n][256 words] --------
__global__ void wprep_kernel(const float* __restrict__ WQ,
                             const float* __restrict__ WK,
                             const float* __restrict__ WV) {
    int n  = blockIdx.x;                 // 0..191
    int kp = threadIdx.x;                // 0..255 (key-dim pair)
    const float* W = (n < 64) ? WQ : (n < 128 ? WK : WV);
    int nc = n & 63;
    float v0 = W[(2*kp)     * 64 + nc];
    float v1 = W[(2*kp + 1) * 64 + nc];
    unsigned hw = packbf(v1, v0);
    float h0 = __uint_as_float(hw << 16);
    float h1 = __uint_as_float(hw & 0xffff0000u);
    unsigned lw = packbf(v1 - h1, v0 - h0);
    g_Wthi[n*256 + kp] = hw;
    g_Wtlo[n*256 + kp] = lw;
}

// ---------------- QKV projection via HMMA (bf16 hi/lo 3-MMA) ----------------
// block: 128 rows x all 192 outputs (Q|K|V), K loop in 64-chunks.
// smem words: xh[128][36] @0, xl @4608, wh[192][36] @9216, wl @16128. total 23040 w.
#define QSMEM_BYTES (23040*4)

__global__ __launch_bounds__(256, 1) void qkv_mma(const float* __restrict__ x) {
    extern __shared__ unsigned qs[];
    unsigned* xh = qs;
    unsigned* xl = qs + 4608;
    unsigned* wh = qs + 9216;
    unsigned* wl = qs + 16128;

    const int tid  = threadIdx.x;
    const int w    = tid >> 5;
    const int lane = tid & 31;
    const int g    = lane >> 2;
    const int t4   = lane & 3;
    const long r0  = (long)blockIdx.x * 128;

    float C[24][4];
    #pragma unroll
    for (int j = 0; j < 24; j++)
        #pragma unroll
        for (int i = 0; i < 4; i++) C[j][i] = 0.f;

    const int bg0 = (w*16 + g) * 36;
    const int bg8 = bg0 + 8*36;

    for (int k0 = 0; k0 < EMB; k0 += 64) {
        // ---- x tile: 128 rows x 64 dims, fp32 -> bf16 hi/lo packed ----
        {
            int r = tid >> 1, h = tid & 1;
            const float4* xp = (const float4*)&x[(r0 + r) * EMB + k0 + h*32];
            #pragma unroll
            for (int i = 0; i < 8; i++) {
                float4 v = xp[i];
                unsigned hw0 = packbf(v.y, v.x);
                unsigned hw1 = packbf(v.w, v.z);
                float hx = __uint_as_float(hw0 << 16);
                float hy = __uint_as_float(hw0 & 0xffff0000u);
                float hz = __uint_as_float(hw1 << 16);
                float hwv = __uint_as_float(hw1 & 0xffff0000u);
                unsigned lw0 = packbf(v.y - hy, v.x - hx);
                unsigned lw1 = packbf(v.w - hwv, v.z - hz);
                int o = r*36 + h*16 + i*2;
                xh[o] = hw0; xh[o+1] = hw1;
                xl[o] = lw0; xl[o+1] = lw1;
            }
        }
        // ---- W^T tile: 192 rows x 32 words (copy from prepped global) ----
        {
            int kw0 = k0 >> 1;
            #pragma unroll
            for (int i = 0; i < 6; i++) {
                int idx = tid + i*256;
                int n = idx >> 3, c4 = idx & 7;
                *(uint4*)(wh + n*36 + c4*4) = *(const uint4*)(g_Wthi + n*256 + kw0 + c4*4);
                *(uint4*)(wl + n*36 + c4*4) = *(const uint4*)(g_Wtlo + n*256 + kw0 + c4*4);
            }
        }
        __syncthreads();

        #pragma unroll
        for (int kk = 0; kk < 4; kk++) {
            int wlo = 8*kk + t4, whi = wlo + 4;
            unsigned ah[4] = { xh[bg0+wlo], xh[bg8+wlo], xh[bg0+whi], xh[bg8+whi] };
            unsigned al[4] = { xl[bg0+wlo], xl[bg8+wlo], xl[bg0+whi], xl[bg8+whi] };
            #pragma unroll
            for (int j = 0; j < 24; j++) {
                const unsigned* bp = wh + (j*8 + g)*36 + wlo;
                const unsigned* blp = wl + (j*8 + g)*36 + wlo;
                unsigned b0 = bp[0], b1 = bp[4];
                unsigned bl0 = blp[0], bl1 = blp[4];
                MMA4(C[j], ah, b0, b1);
                MMA4(C[j], ah, bl0, bl1);
                MMA4(C[j], al, b0, b1);
            }
        }
        __syncthreads();
    }

    // ---- epilogue: Q (j 0..7), K (j 8..15) -> packed bf16 hi/lo global ----
    const long rowg = r0 + w*16 + g;
    #pragma unroll
    for (int j = 0; j < 16; j++) {
        unsigned* oh = (j < 8) ? g_Qhi : g_Khi;
        unsigned* ol = (j < 8) ? g_Qlo : g_Klo;
        int wi = (j & 7)*4 + t4;
        {
            float c0 = C[j][0], c1 = C[j][1];
            unsigned hw = packbf(c1, c0);
            float h0 = __uint_as_float(hw << 16);
            float h1 = __uint_as_float(hw & 0xffff0000u);
            oh[rowg*32 + wi] = hw;
            ol[rowg*32 + wi] = packbf(c1 - h1, c0 - h0);
        }
        {
            float c0 = C[j][2], c1 = C[j][3];
            unsigned hw = packbf(c1, c0);
            float h0 = __uint_as_float(hw << 16);
            float h1 = __uint_as_float(hw & 0xffff0000u);
            oh[(rowg+8)*32 + wi] = hw;
            ol[(rowg+8)*32 + wi] = packbf(c1 - h1, c0 - h0);
        }
    }

    // ---- V (j 16..23): stage fp32 in smem, transpose+pack to g_Vt ----
    float* vs = (float*)qs;   // [128][66] floats (33792 B, fits below wh)
    #pragma unroll
    for (int j = 16; j < 24; j++) {
        int col = (j - 16)*8 + 2*t4;
        *(float2*)&vs[(w*16 + g)*66 + col]     = make_float2(C[j][0], C[j][1]);
        *(float2*)&vs[(w*16 + g + 8)*66 + col] = make_float2(C[j][2], C[j][3]);
    }
    __syncthreads();

    {
        int b   = (int)(r0 >> 12);
        int kpb = (int)(r0 & 4095) >> 1;   // keypair base within batch
        int kp  = tid & 63;
        int d0  = (tid >> 6) * 16;
        #pragma unroll
        for (int i = 0; i < 16; i++) {
            int d = d0 + i;
            float v0 = vs[(2*kp)*66 + d];
            float v1 = vs[(2*kp + 1)*66 + d];
            unsigned hw = packbf(v1, v0);
            float h0 = __uint_as_float(hw << 16);
            float h1 = __uint_as_float(hw & 0xffff0000u);
            unsigned lw = packbf(v1 - h1, v0 - h0);
            size_t wi = ((size_t)(b*64 + d)) * 2048 + kpb + kp;
            g_Vthi[wi] = hw;
            g_Vtlo[wi] = lw;
        }
    }
}

// ---------------- HMMA flash attention (no online max), key-split ----------------
// smem: Khi[128][36]w, Klo[128][36]w, Vthi[64][68]w, Vtlo[64][68]w  (words)
#define S_KHI 0
#define S_KLO 18432
#define S_VHI 36864
#define S_VLO 54272
#define SMEM_BYTES 71680

__global__ __launch_bounds__(256, 1) void attn_mma() {
    extern __shared__ char smem[];
    unsigned* Khs = (unsigned*)(smem + S_KHI);
    unsigned* Kls = (unsigned*)(smem + S_KLO);
    unsigned* Vhs = (unsigned*)(smem + S_VHI);
    unsigned* Vls = (unsigned*)(smem + S_VLO);

    const int tid  = threadIdx.x;
    const int w    = tid >> 5;
    const int lane = tid & 31;
    const int g    = lane >> 2;
    const int t4   = lane & 3;

    // decode (m, split)
    int rid = blockIdx.x, m = 0, split = 0;
    #pragma unroll 1
    for (int mm = 0; mm < NMT; mm++) {
        int c = (mm + TPB) >> 3;
        if (rid < c) { m = mm; split = rid; break; }
        rid -= c;
    }
    const int b   = blockIdx.y;
    const int kt0 = split * TPB;
    const int kt1 = (kt0 + TPB < m + 1) ? (kt0 + TPB) : (m + 1);
    const long brow = (long)b * SEQ;
    const int rg = m * MT + w * 16 + g;    // global q row (low of pair)

    // Q fragments (persist across tiles)
    unsigned qh[4][4], ql[4][4];
    {
        long base0 = (brow + rg) * 32;
        long base8 = base0 + 8 * 32;
        #pragma unroll
        for (int kk = 0; kk < 4; kk++) {
            int wlo = 8*kk + t4, whi = wlo + 4;
            qh[kk][0] = g_Qhi[base0 + wlo]; qh[kk][1] = g_Qhi[base8 + wlo];
            qh[kk][2] = g_Qhi[base0 + whi]; qh[kk][3] = g_Qhi[base8 + whi];
            ql[kk][0] = g_Qlo[base0 + wlo]; ql[kk][1] = g_Qlo[base8 + wlo];
            ql[kk][2] = g_Qlo[base0 + whi]; ql[kk][3] = g_Qlo[base8 + whi];
        }
    }

    float O[8][4];
    #pragma unroll
    for (int i = 0; i < 8; i++)
        #pragma unroll
        for (int j = 0; j < 4; j++) O[i][j] = 0.f;
    float lacc0 = 0.f, lacc1 = 0.f;

    for (int kt = kt0; kt < kt1; kt++) {
        // ---- load K hi/lo (128 rows x 32 words) into smem ----
        {
            const uint4* KH = (const uint4*)g_Khi + (brow + (long)kt * KT) * 8;
            const uint4* KL = (const uint4*)g_Klo + (brow + (long)kt * KT) * 8;
            #pragma unroll
            for (int i = 0; i < 4; i++) {
                int idx = tid + i * 256;
                int r = idx >> 3, c4 = idx & 7;
                *(uint4*)(Khs + r*36 + c4*4) = KH[r*8 + c4];
                *(uint4*)(Kls + r*36 + c4*4) = KL[r*8 + c4];
            }
            // ---- Vt hi/lo: 64 rows x 64 words = 1024 uint4 each ----
            #pragma unroll
            for (int i = 0; i < 4; i++) {
                int idx = tid + i * 256;
                int d = idx >> 4, c4 = idx & 15;
                size_t vbase = ((size_t)(b*64 + d)) * 512 + (size_t)kt * 16 + c4;
                *(uint4*)(Vhs + d*68 + c4*4) = ((const uint4*)g_Vthi)[vbase];
                *(uint4*)(Vls + d*68 + c4*4) = ((const uint4*)g_Vtlo)[vbase];
            }
        }
        __syncthreads();

        // ---- S = Qhi*Khi + Qhi*Klo + Qlo*Khi  (16 n-tiles of 8 keys) ----
        float S[16][4];
        #pragma unroll
        for (int j = 0; j < 16; j++)
            #pragma unroll
            for (int r = 0; r < 4; r++) S[j][r] = 0.f;

        #pragma unroll
        for (int kk = 0; kk < 4; kk++) {
            #pragma unroll
            for (int j = 0; j < 16; j++) {
                const unsigned* kh = Khs + (j*8 + g)*36 + 8*kk + t4;
                const unsigned* kl = Kls + (j*8 + g)*36 + 8*kk + t4;
                unsigned bh0 = kh[0], bh1 = kh[4];
                unsigned bl0 = kl[0], bl1 = kl[4];
                MMA4(S[j], qh[kk], bh0, bh1);
                MMA4(S[j], qh[kk], bl0, bl1);
                MMA4(S[j], ql[kk], bh0, bh1);
            }
        }

        // ---- softmax (no max-sub) + build P hi/lo A-fragments ----
        const int diag = (kt == m);
        const int kbase = kt * KT;
        unsigned ph[8][4], pl[8][4];
        #pragma unroll
        for (int j = 0; j < 16; j++) {
            float p0 = exp2f(S[j][0] * SCALE_LOG2E);
            float p1 = exp2f(S[j][1] * SCALE_LOG2E);
            float p2 = exp2f(S[j][2] * SCALE_LOG2E);
            float p3 = exp2f(S[j][3] * SCALE_LOG2E);
            if (diag) {
                int col = kbase + j*8 + 2*t4;
                if (col     > rg)     p0 = 0.f;
                if (col + 1 > rg)     p1 = 0.f;
                if (col     > rg + 8) p2 = 0.f;
                if (col + 1 > rg + 8) p3 = 0.f;
            }
            lacc0 += p0 + p1;
            lacc1 += p2 + p3;
            unsigned h01 = packbf(p1, p0);
            unsigned h23 = packbf(p3, p2);
            float r0 = p0 - __uint_as_float(h01 << 16);
            float r1 = p1 - __uint_as_float(h01 & 0xffff0000u);
            float r2 = p2 - __uint_as_float(h23 << 16);
            float r3 = p3 - __uint_as_float(h23 & 0xffff0000u);
            int kk2 = j >> 1, hf = (j & 1) * 2;
            ph[kk2][hf]     = h01;
            ph[kk2][hf + 1] = h23;
            pl[kk2][hf]     = packbf(r1, r0);
            pl[kk2][hf + 1] = packbf(r3, r2);
        }

        // ---- O += Phi*Vhi + Phi*Vlo + Plo*Vhi ----
        #pragma unroll
        for (int kk2 = 0; kk2 < 8; kk2++) {
            #pragma unroll
            for (int n2 = 0; n2 < 8; n2++) {
                const unsigned* vh = Vhs + (n2*8 + g)*68 + 8*kk2 + t4;
                const unsigned* vl = Vls + (n2*8 + g)*68 + 8*kk2 + t4;
                unsigned bh0 = vh[0], bh1 = vh[4];
                unsigned bl0 = vl[0], bl1 = vl[4];
                MMA4(O[n2], ph[kk2], bh0, bh1);
                MMA4(O[n2], ph[kk2], bl0, bl1);
                MMA4(O[n2], pl[kk2], bh0, bh1);
            }
        }
        __syncthreads();
    }

    // ---- reduce l over quad, write partials ----
    lacc0 += __shfl_xor_sync(0xffffffffu, lacc0, 1);
    lacc0 += __shfl_xor_sync(0xffffffffu, lacc0, 2);
    lacc1 += __shfl_xor_sync(0xffffffffu, lacc1, 1);
    lacc1 += __shfl_xor_sync(0xffffffffu, lacc1, 2);

    const int pidx = (b * NMT + m) * MAXSPLIT + split;
    if (t4 == 0) {
        g_Lpart[pidx*128 + w*16 + g]     = lacc0;
        g_Lpart[pidx*128 + w*16 + g + 8] = lacc1;
    }
    float* op = g_Opart + ((size_t)pidx*128 + w*16 + g) * 64;
    #pragma unroll
    for (int n2 = 0; n2 < 8; n2++) {
        *(float2*)&op[n2*8 + 2*t4]          = make_float2(O[n2][0], O[n2][1]);
        *(float2*)&op[8*64 + n2*8 + 2*t4]   = make_float2(O[n2][2], O[n2][3]);
    }
}

// ---------------- combine split partials (float4) ----------------
__global__ void combine_kernel(float* __restrict__ out) {
    int idx4 = blockIdx.x * blockDim.x + threadIdx.x;
    if (idx4 >= BS * HD / 4) return;
    int row = idx4 >> 4, d4 = idx4 & 15;
    int b = row >> 12;
    int s_in_b = row & 4095;
    int m = s_in_b >> 7, r = s_in_b & 127;
    int nsp = (m + TPB) >> 3;
    int p0 = (b * NMT + m) * MAXSPLIT;

    float4 sO = make_float4(0.f, 0.f, 0.f, 0.f);
    float sL = 0.f;
    #pragma unroll 1
    for (int s = 0; s < nsp; s++) {
        int p = p0 + s;
        float4 v = *(const float4*)&g_Opart[((size_t)p * 128 + r) * 64 + d4*4];
        sO.x += v.x; sO.y += v.y; sO.z += v.z; sO.w += v.w;
        sL += g_Lpart[p * 128 + r];
    }
    float inv = 1.f / sL;
    *(float4*)&out[idx4*4] = make_float4(sO.x*inv, sO.y*inv, sO.z*inv, sO.w*inv);
}

extern "C" void kernel_launch(void* const* d_in, const int* in_sizes, int n_in,
                              void* d_out, int out_size) {
    const float* x  = (const float*)d_in[0];
    const float* WQ = (const float*)d_in[1];
    const float* WK = (const float*)d_in[2];
    const float* WV = (const float*)d_in[3];
    float* out = (float*)d_out;

    cudaFuncSetAttribute(qkv_mma,  cudaFuncAttributeMaxDynamicSharedMemorySize, QSMEM_BYTES);
    cudaFuncSetAttribute(attn_mma, cudaFuncAttributeMaxDynamicSharedMemorySize, SMEM_BYTES);

    wprep_kernel<<<192, 256>>>(WQ, WK, WV);
    qkv_mma<<<BS / 128, 256, QSMEM_BYTES>>>(x);
    attn_mma<<<dim3(BLKS_PER_B, BATCH), 256, SMEM_BYTES>>>();
    combine_kernel<<<(BS * HD / 4 + 255) / 256, 256>>>(out);
}

// round 7
// speedup vs baseline: 5.9820x; 1.2291x over previous
#include <cuda_runtime.h>
#include <cuda_fp16.h>
#include <math.h>
#include <stdint.h>

#define BATCH 4
#define SEQ   4096
#define EMB   512
#define HD    64
#define BS    (BATCH*SEQ)
#define MT    128
#define NMT   (SEQ/MT)            // 32
#define KT    128
#define TPB   8                   // max key tiles per block
#define BLKS_PER_B 80             // sum_m ceil((m+1)/8)
#define MAXSPLIT 4
#define SCALE_LOG2E 0.06375872036f   // log2(e)/sqrt(512)

// ---------------- device scratch ----------------
__device__ unsigned g_Qh[BS*32];                    // packed fp16 pairs, [row][32 words]
__device__ unsigned g_Kh[BS*32];
__device__ unsigned g_Vth[BATCH*64*2048];           // V^T packed key-pairs, [b*64+d][2048]
__device__ unsigned g_Wth[192*256];                 // W^T packed: [n(Q64|K64|V64)][256 kw]
__device__ float    g_Opart[(size_t)BATCH*NMT*MAXSPLIT*MT*HD];
__device__ float    g_Lpart[BATCH*NMT*MAXSPLIT*MT];

// pack two fp32 -> fp16x2 (first arg = odd/upper half, second = even/lower)
static __device__ __forceinline__ unsigned packhf(float o, float e) {
    unsigned r;
    asm("cvt.rn.f16x2.f32 %0, %1, %2;" : "=r"(r) : "f"(o), "f"(e));
    return r;
}
static __device__ __forceinline__ uint32_t smem_u32(const void* p) {
    uint32_t a;
    asm("{ .reg .u64 t; cvta.to.shared.u64 t, %1; cvt.u32.u64 %0, t; }" : "=r"(a) : "l"(p));
    return a;
}
static __device__ __forceinline__ void cpa16(uint32_t s, const void* g) {
    asm volatile("cp.async.cg.shared.global [%0], [%1], 16;" :: "r"(s), "l"(g));
}
#define CPA_COMMIT() asm volatile("cp.async.commit_group;" ::: "memory")
#define CPA_WAIT0()  asm volatile("cp.async.wait_group 0;" ::: "memory")

#define MMAH(C, A, b0v, b1v)                                                     \
    asm volatile("mma.sync.aligned.m16n8k16.row.col.f32.f16.f16.f32 "            \
        "{%0,%1,%2,%3}, {%4,%5,%6,%7}, {%8,%9}, {%0,%1,%2,%3};"                  \
        : "+f"((C)[0]), "+f"((C)[1]), "+f"((C)[2]), "+f"((C)[3])                 \
        : "r"((A)[0]), "r"((A)[1]), "r"((A)[2]), "r"((A)[3]), "r"(b0v), "r"(b1v))

// ---------------- W^T prep: [n=192][k=512] -> packed fp16 [n][256 words] --------
__global__ void wprep_kernel(const float* __restrict__ WQ,
                             const float* __restrict__ WK,
                             const float* __restrict__ WV) {
    int n  = blockIdx.x;                 // 0..191
    int kp = threadIdx.x;                // 0..255 (key-dim pair)
    const float* W = (n < 64) ? WQ : (n < 128 ? WK : WV);
    int nc = n & 63;
    float v0 = W[(2*kp)     * 64 + nc];
    float v1 = W[(2*kp + 1) * 64 + nc];
    g_Wth[n*256 + kp] = packhf(v1, v0);
}

// ---------------- QKV projection via single-fp16 HMMA ----------------
// smem words: xh[128][36] @0, wh[192][36] @4608. total 11520 w = 46080 B.
#define QSMEM_BYTES (11520*4)

__global__ __launch_bounds__(256, 1) void qkv_mma(const float* __restrict__ x) {
    extern __shared__ unsigned qs[];
    unsigned* xh = qs;
    unsigned* wh = qs + 4608;

    const int tid  = threadIdx.x;
    const int w    = tid >> 5;
    const int lane = tid & 31;
    const int g    = lane >> 2;
    const int t4   = lane & 3;
    const long r0  = (long)blockIdx.x * 128;

    float C[24][4];
    #pragma unroll
    for (int j = 0; j < 24; j++)
        #pragma unroll
        for (int i = 0; i < 4; i++) C[j][i] = 0.f;

    const int bg0 = (w*16 + g) * 36;
    const int bg8 = bg0 + 8*36;

    for (int k0 = 0; k0 < EMB; k0 += 64) {
        // ---- x tile: 128 rows x 64 dims, fp32 -> fp16 packed ----
        {
            int r = tid >> 1, h = tid & 1;
            const float4* xp = (const float4*)&x[(r0 + r) * EMB + k0 + h*32];
            #pragma unroll
            for (int i = 0; i < 8; i++) {
                float4 v = xp[i];
                int o = r*36 + h*16 + i*2;
                xh[o]   = packhf(v.y, v.x);
                xh[o+1] = packhf(v.w, v.z);
            }
        }
        // ---- W^T tile: 192 rows x 32 words ----
        {
            int kw0 = k0 >> 1;
            #pragma unroll
            for (int i = 0; i < 6; i++) {
                int idx = tid + i*256;
                int n = idx >> 3, c4 = idx & 7;
                *(uint4*)(wh + n*36 + c4*4) = *(const uint4*)(g_Wth + n*256 + kw0 + c4*4);
            }
        }
        __syncthreads();

        #pragma unroll
        for (int kk = 0; kk < 4; kk++) {
            int wlo = 8*kk + t4, whi = wlo + 4;
            unsigned ah[4] = { xh[bg0+wlo], xh[bg8+wlo], xh[bg0+whi], xh[bg8+whi] };
            #pragma unroll
            for (int j = 0; j < 24; j++) {
                const unsigned* bp = wh + (j*8 + g)*36 + wlo;
                MMAH(C[j], ah, bp[0], bp[4]);
            }
        }
        __syncthreads();
    }

    // ---- epilogue: Q (j 0..7), K (j 8..15) -> packed fp16 global ----
    const long rowg = r0 + w*16 + g;
    #pragma unroll
    for (int j = 0; j < 16; j++) {
        unsigned* oh = (j < 8) ? g_Qh : g_Kh;
        int wi = (j & 7)*4 + t4;
        oh[rowg*32 + wi]     = packhf(C[j][1], C[j][0]);
        oh[(rowg+8)*32 + wi] = packhf(C[j][3], C[j][2]);
    }

    // ---- V (j 16..23): stage fp32 in smem, transpose+pack to g_Vth ----
    float* vs = (float*)qs;   // [128][66] floats = 8448 w, fits in 11520 w
    #pragma unroll
    for (int j = 16; j < 24; j++) {
        int col = (j - 16)*8 + 2*t4;
        *(float2*)&vs[(w*16 + g)*66 + col]     = make_float2(C[j][0], C[j][1]);
        *(float2*)&vs[(w*16 + g + 8)*66 + col] = make_float2(C[j][2], C[j][3]);
    }
    __syncthreads();

    {
        int b   = (int)(r0 >> 12);
        int kpb = (int)(r0 & 4095) >> 1;   // keypair base within batch
        int kp  = tid & 63;
        int d0  = (tid >> 6) * 16;
        #pragma unroll
        for (int i = 0; i < 16; i++) {
            int d = d0 + i;
            float v0 = vs[(2*kp)*66 + d];
            float v1 = vs[(2*kp + 1)*66 + d];
            g_Vth[((size_t)(b*64 + d)) * 2048 + kpb + kp] = packhf(v1, v0);
        }
    }
}

// ---------------- fp16 HMMA flash attention, cp.async double-buffered ----------------
// buffer (words): K[128][36]=4608, V[64][68]=4352 -> 8960/buffer; 2 buffers = 17920 w.
#define BUF_W   8960
#define BK_OFF  0
#define BV_OFF  4608
#define SMEM_BYTES (17920*4)

static __device__ __forceinline__ void attn_issue(uint32_t sbase, int bufw,
                                                  int tid, int b, long brow, int kt) {
    const uint4* KH = (const uint4*)g_Kh + (brow + (long)kt * KT) * 8;
    uint32_t kb = sbase + (bufw + BK_OFF) * 4;
    #pragma unroll
    for (int i = 0; i < 4; i++) {
        int idx = tid + i * 256;
        int r = idx >> 3, c4 = idx & 7;
        cpa16(kb + (r*36 + c4*4)*4, &KH[r*8 + c4]);
    }
    uint32_t vb = sbase + (bufw + BV_OFF) * 4;
    #pragma unroll
    for (int i = 0; i < 4; i++) {
        int idx = tid + i * 256;
        int d = idx >> 4, c4 = idx & 15;
        cpa16(vb + (d*68 + c4*4)*4,
              (const uint4*)g_Vth + ((size_t)(b*64 + d)) * 512 + (size_t)kt * 16 + c4);
    }
}

__global__ __launch_bounds__(256, 1) void attn_mma() {
    extern __shared__ unsigned smw[];
    const uint32_t sbase = smem_u32(smw);

    const int tid  = threadIdx.x;
    const int w    = tid >> 5;
    const int lane = tid & 31;
    const int g    = lane >> 2;
    const int t4   = lane & 3;

    // decode (m, split)
    int rid = blockIdx.x, m = 0, split = 0;
    #pragma unroll 1
    for (int mm = 0; mm < NMT; mm++) {
        int c = (mm + TPB) >> 3;
        if (rid < c) { m = mm; split = rid; break; }
        rid -= c;
    }
    const int b   = blockIdx.y;
    const int kt0 = split * TPB;
    const int kt1 = (kt0 + TPB < m + 1) ? (kt0 + TPB) : (m + 1);
    const long brow = (long)b * SEQ;
    const int rg = m * MT + w * 16 + g;    // global q row (low of pair)

    // Q fragments (persist across tiles)
    unsigned qh[4][4];
    {
        long base0 = (brow + rg) * 32;
        long base8 = base0 + 8 * 32;
        #pragma unroll
        for (int kk = 0; kk < 4; kk++) {
            int wlo = 8*kk + t4, whi = wlo + 4;
            qh[kk][0] = g_Qh[base0 + wlo]; qh[kk][1] = g_Qh[base8 + wlo];
            qh[kk][2] = g_Qh[base0 + whi]; qh[kk][3] = g_Qh[base8 + whi];
        }
    }

    float O[8][4];
    #pragma unroll
    for (int i = 0; i < 8; i++)
        #pragma unroll
        for (int j = 0; j < 4; j++) O[i][j] = 0.f;
    float lacc0 = 0.f, lacc1 = 0.f;

    // prologue: prefetch first tile into buffer 0
    attn_issue(sbase, 0, tid, b, brow, kt0);
    CPA_COMMIT();
    int cur = 0;

    for (int kt = kt0; kt < kt1; kt++) {
        CPA_WAIT0();
        __syncthreads();                 // current buffer ready; prev readers done
        if (kt + 1 < kt1) {
            attn_issue(sbase, (cur ^ 1) * BUF_W, tid, b, brow, kt + 1);
            CPA_COMMIT();
        }
        const unsigned* Khs = smw + cur * BUF_W + BK_OFF;
        const unsigned* Vhs = smw + cur * BUF_W + BV_OFF;

        // ---- S = Q K^T (16 n-tiles of 8 keys) ----
        float S[16][4];
        #pragma unroll
        for (int j = 0; j < 16; j++)
            #pragma unroll
            for (int r = 0; r < 4; r++) S[j][r] = 0.f;

        #pragma unroll
        for (int kk = 0; kk < 4; kk++) {
            #pragma unroll
            for (int j = 0; j < 16; j++) {
                const unsigned* kh = Khs + (j*8 + g)*36 + 8*kk + t4;
                MMAH(S[j], qh[kk], kh[0], kh[4]);
            }
        }

        // ---- softmax (no max-sub) + build P fp16 A-fragments ----
        const int diag = (kt == m);
        const int kbase = kt * KT;
        unsigned ph[8][4];
        #pragma unroll
        for (int j = 0; j < 16; j++) {
            float p0 = exp2f(S[j][0] * SCALE_LOG2E);
            float p1 = exp2f(S[j][1] * SCALE_LOG2E);
            float p2 = exp2f(S[j][2] * SCALE_LOG2E);
            float p3 = exp2f(S[j][3] * SCALE_LOG2E);
            if (diag) {
                int col = kbase + j*8 + 2*t4;
                if (col     > rg)     p0 = 0.f;
                if (col + 1 > rg)     p1 = 0.f;
                if (col     > rg + 8) p2 = 0.f;
                if (col + 1 > rg + 8) p3 = 0.f;
            }
            lacc0 += p0 + p1;
            lacc1 += p2 + p3;
            int kk2 = j >> 1, hf = (j & 1) * 2;
            ph[kk2][hf]     = packhf(p1, p0);
            ph[kk2][hf + 1] = packhf(p3, p2);
        }

        // ---- O += P V ----
        #pragma unroll
        for (int kk2 = 0; kk2 < 8; kk2++) {
            #pragma unroll
            for (int n2 = 0; n2 < 8; n2++) {
                const unsigned* vh = Vhs + (n2*8 + g)*68 + 8*kk2 + t4;
                MMAH(O[n2], ph[kk2], vh[0], vh[4]);
            }
        }
        cur ^= 1;
    }

    // ---- reduce l over quad, write partials ----
    lacc0 += __shfl_xor_sync(0xffffffffu, lacc0, 1);
    lacc0 += __shfl_xor_sync(0xffffffffu, lacc0, 2);
    lacc1 += __shfl_xor_sync(0xffffffffu, lacc1, 1);
    lacc1 += __shfl_xor_sync(0xffffffffu, lacc1, 2);

    const int pidx = (b * NMT + m) * MAXSPLIT + split;
    if (t4 == 0) {
        g_Lpart[pidx*128 + w*16 + g]     = lacc0;
        g_Lpart[pidx*128 + w*16 + g + 8] = lacc1;
    }
    float* op = g_Opart + ((size_t)pidx*128 + w*16 + g) * 64;
    #pragma unroll
    for (int n2 = 0; n2 < 8; n2++) {
        *(float2*)&op[n2*8 + 2*t4]          = make_float2(O[n2][0], O[n2][1]);
        *(float2*)&op[8*64 + n2*8 + 2*t4]   = make_float2(O[n2][2], O[n2][3]);
    }
}

// ---------------- combine split partials (float4) ----------------
__global__ void combine_kernel(float* __restrict__ out) {
    int idx4 = blockIdx.x * blockDim.x + threadIdx.x;
    if (idx4 >= BS * HD / 4) return;
    int row = idx4 >> 4, d4 = idx4 & 15;
    int b = row >> 12;
    int s_in_b = row & 4095;
    int m = s_in_b >> 7, r = s_in_b & 127;
    int nsp = (m + TPB) >> 3;
    int p0 = (b * NMT + m) * MAXSPLIT;

    float4 sO = make_float4(0.f, 0.f, 0.f, 0.f);
    float sL = 0.f;
    #pragma unroll 1
    for (int s = 0; s < nsp; s++) {
        int p = p0 + s;
        float4 v = *(const float4*)&g_Opart[((size_t)p * 128 + r) * 64 + d4*4];
        sO.x += v.x; sO.y += v.y; sO.z += v.z; sO.w += v.w;
        sL += g_Lpart[p * 128 + r];
    }
    float inv = 1.f / sL;
    *(float4*)&out[idx4*4] = make_float4(sO.x*inv, sO.y*inv, sO.z*inv, sO.w*inv);
}

extern "C" void kernel_launch(void* const* d_in, const int* in_sizes, int n_in,
                              void* d_out, int out_size) {
    const float* x  = (const float*)d_in[0];
    const float* WQ = (const float*)d_in[1];
    const float* WK = (const float*)d_in[2];
    const float* WV = (const float*)d_in[3];
    float* out = (float*)d_out;

    cudaFuncSetAttribute(qkv_mma,  cudaFuncAttributeMaxDynamicSharedMemorySize, QSMEM_BYTES);
    cudaFuncSetAttribute(attn_mma, cudaFuncAttributeMaxDynamicSharedMemorySize, SMEM_BYTES);

    wprep_kernel<<<192, 256>>>(WQ, WK, WV);
    qkv_mma<<<BS / 128, 256, QSMEM_BYTES>>>(x);
    attn_mma<<<dim3(BLKS_PER_B, BATCH), 256, SMEM_BYTES>>>();
    combine_kernel<<<(BS * HD / 4 + 255) / 256, 256>>>(out);
}

// round 8
// speedup vs baseline: 8.5182x; 1.4240x over previous
#include <cuda_runtime.h>
#include <cuda_fp16.h>
#include <math.h>
#include <stdint.h>

#define BATCH 4
#define SEQ   4096
#define EMB   512
#define HD    64
#define BS    (BATCH*SEQ)
#define MT    128
#define NMT   (SEQ/MT)            // 32
#define KT    128
#define TPB   8                   // max key tiles per block
#define BLKS_PER_B 80             // sum_m ceil((m+1)/8)
#define MAXSPLIT 4
#define SCALE_LOG2E 0.06375872036f   // log2(e)/sqrt(512)

// ---------------- device scratch ----------------
__device__ unsigned g_Qh[BS*32];                    // packed fp16 pairs, [row][32 words]
__device__ unsigned g_Kh[BS*32];
__device__ unsigned g_Vth[BATCH*64*2048];           // V^T packed key-pairs, [b*64+d][2048]
__device__ unsigned g_Wth[192*256];                 // W^T packed: [n(Q64|K64|V64)][256 kw]
__device__ float    g_Opart[(size_t)BATCH*NMT*MAXSPLIT*MT*HD];
__device__ float    g_Lpart[BATCH*NMT*MAXSPLIT*MT];

// pack two fp32 -> fp16x2 (first arg = odd/upper half, second = even/lower)
static __device__ __forceinline__ unsigned packhf(float o, float e) {
    unsigned r;
    asm("cvt.rn.f16x2.f32 %0, %1, %2;" : "=r"(r) : "f"(o), "f"(e));
    return r;
}
// fast exp2 via MUFU (guaranteed, independent of compile flags)
static __device__ __forceinline__ float ex2(float x) {
    float r;
    asm("ex2.approx.ftz.f32 %0, %1;" : "=f"(r) : "f"(x));
    return r;
}
static __device__ __forceinline__ uint32_t smem_u32(const void* p) {
    uint32_t a;
    asm("{ .reg .u64 t; cvta.to.shared.u64 t, %1; cvt.u32.u64 %0, t; }" : "=r"(a) : "l"(p));
    return a;
}
static __device__ __forceinline__ void cpa16(uint32_t s, const void* g) {
    asm volatile("cp.async.cg.shared.global [%0], [%1], 16;" :: "r"(s), "l"(g));
}
#define CPA_COMMIT() asm volatile("cp.async.commit_group;" ::: "memory")
#define CPA_WAIT0()  asm volatile("cp.async.wait_group 0;" ::: "memory")

#define MMAH(C, A, b0v, b1v)                                                     \
    asm volatile("mma.sync.aligned.m16n8k16.row.col.f32.f16.f16.f32 "            \
        "{%0,%1,%2,%3}, {%4,%5,%6,%7}, {%8,%9}, {%0,%1,%2,%3};"                  \
        : "+f"((C)[0]), "+f"((C)[1]), "+f"((C)[2]), "+f"((C)[3])                 \
        : "r"((A)[0]), "r"((A)[1]), "r"((A)[2]), "r"((A)[3]), "r"(b0v), "r"(b1v))

// ---------------- W^T prep: [n=192][k=512] -> packed fp16 [n][256 words] --------
__global__ void wprep_kernel(const float* __restrict__ WQ,
                             const float* __restrict__ WK,
                             const float* __restrict__ WV) {
    int n  = blockIdx.x;                 // 0..191
    int kp = threadIdx.x;                // 0..255 (key-dim pair)
    const float* W = (n < 64) ? WQ : (n < 128 ? WK : WV);
    int nc = n & 63;
    float v0 = W[(2*kp)     * 64 + nc];
    float v1 = W[(2*kp + 1) * 64 + nc];
    g_Wth[n*256 + kp] = packhf(v1, v0);
}

// ---------------- QKV projection via single-fp16 HMMA ----------------
// smem words: xh[128][36] @0, wh[192][36] @4608. total 11520 w = 46080 B.
#define QSMEM_BYTES (11520*4)

__global__ __launch_bounds__(256, 1) void qkv_mma(const float* __restrict__ x) {
    extern __shared__ unsigned qs[];
    unsigned* xh = qs;
    unsigned* wh = qs + 4608;

    const int tid  = threadIdx.x;
    const int w    = tid >> 5;
    const int lane = tid & 31;
    const int g    = lane >> 2;
    const int t4   = lane & 3;
    const long r0  = (long)blockIdx.x * 128;

    float C[24][4];
    #pragma unroll
    for (int j = 0; j < 24; j++)
        #pragma unroll
        for (int i = 0; i < 4; i++) C[j][i] = 0.f;

    const int bg0 = (w*16 + g) * 36;
    const int bg8 = bg0 + 8*36;

    for (int k0 = 0; k0 < EMB; k0 += 64) {
        // ---- x tile: 128 rows x 64 dims, fp32 -> fp16 packed ----
        {
            int r = tid >> 1, h = tid & 1;
            const float4* xp = (const float4*)&x[(r0 + r) * EMB + k0 + h*32];
            #pragma unroll
            for (int i = 0; i < 8; i++) {
                float4 v = xp[i];
                int o = r*36 + h*16 + i*2;
                xh[o]   = packhf(v.y, v.x);
                xh[o+1] = packhf(v.w, v.z);
            }
        }
        // ---- W^T tile: 192 rows x 32 words ----
        {
            int kw0 = k0 >> 1;
            #pragma unroll
            for (int i = 0; i < 6; i++) {
                int idx = tid + i*256;
                int n = idx >> 3, c4 = idx & 7;
                *(uint4*)(wh + n*36 + c4*4) = *(const uint4*)(g_Wth + n*256 + kw0 + c4*4);
            }
        }
        __syncthreads();

        #pragma unroll
        for (int kk = 0; kk < 4; kk++) {
            int wlo = 8*kk + t4, whi = wlo + 4;
            unsigned ah[4] = { xh[bg0+wlo], xh[bg8+wlo], xh[bg0+whi], xh[bg8+whi] };
            #pragma unroll
            for (int j = 0; j < 24; j++) {
                const unsigned* bp = wh + (j*8 + g)*36 + wlo;
                MMAH(C[j], ah, bp[0], bp[4]);
            }
        }
        __syncthreads();
    }

    // ---- epilogue: Q (j 0..7), K (j 8..15) -> packed fp16 global ----
    const long rowg = r0 + w*16 + g;
    #pragma unroll
    for (int j = 0; j < 16; j++) {
        unsigned* oh = (j < 8) ? g_Qh : g_Kh;
        int wi = (j & 7)*4 + t4;
        oh[rowg*32 + wi]     = packhf(C[j][1], C[j][0]);
        oh[(rowg+8)*32 + wi] = packhf(C[j][3], C[j][2]);
    }

    // ---- V (j 16..23): stage fp32 in smem, transpose+pack to g_Vth ----
    float* vs = (float*)qs;   // [128][66] floats = 8448 w, fits in 11520 w
    #pragma unroll
    for (int j = 16; j < 24; j++) {
        int col = (j - 16)*8 + 2*t4;
        *(float2*)&vs[(w*16 + g)*66 + col]     = make_float2(C[j][0], C[j][1]);
        *(float2*)&vs[(w*16 + g + 8)*66 + col] = make_float2(C[j][2], C[j][3]);
    }
    __syncthreads();

    {
        int b   = (int)(r0 >> 12);
        int kpb = (int)(r0 & 4095) >> 1;   // keypair base within batch
        int kp  = tid & 63;
        int d0  = (tid >> 6) * 16;
        #pragma unroll
        for (int i = 0; i < 16; i++) {
            int d = d0 + i;
            float v0 = vs[(2*kp)*66 + d];
            float v1 = vs[(2*kp + 1)*66 + d];
            g_Vth[((size_t)(b*64 + d)) * 2048 + kpb + kp] = packhf(v1, v0);
        }
    }
}

// ---------------- fp16 HMMA flash attention, cp.async double-buffered ----------------
// buffer (words): K[128][36]=4608, V[64][68]=4352 -> 8960/buffer; 2 buffers = 17920 w.
#define BUF_W   8960
#define BK_OFF  0
#define BV_OFF  4608
#define SMEM_BYTES (17920*4)

static __device__ __forceinline__ void attn_issue(uint32_t sbase, int bufw,
                                                  int tid, int b, long brow, int kt) {
    const uint4* KH = (const uint4*)g_Kh + (brow + (long)kt * KT) * 8;
    uint32_t kb = sbase + (bufw + BK_OFF) * 4;
    #pragma unroll
    for (int i = 0; i < 4; i++) {
        int idx = tid + i * 256;
        int r = idx >> 3, c4 = idx & 7;
        cpa16(kb + (r*36 + c4*4)*4, &KH[r*8 + c4]);
    }
    uint32_t vb = sbase + (bufw + BV_OFF) * 4;
    #pragma unroll
    for (int i = 0; i < 4; i++) {
        int idx = tid + i * 256;
        int d = idx >> 4, c4 = idx & 15;
        cpa16(vb + (d*68 + c4*4)*4,
              (const uint4*)g_Vth + ((size_t)(b*64 + d)) * 512 + (size_t)kt * 16 + c4);
    }
}

__global__ __launch_bounds__(256, 1) void attn_mma() {
    extern __shared__ unsigned smw[];
    const uint32_t sbase = smem_u32(smw);

    const int tid  = threadIdx.x;
    const int w    = tid >> 5;
    const int lane = tid & 31;
    const int g    = lane >> 2;
    const int t4   = lane & 3;

    // decode (m, split)
    int rid = blockIdx.x, m = 0, split = 0;
    #pragma unroll 1
    for (int mm = 0; mm < NMT; mm++) {
        int c = (mm + TPB) >> 3;
        if (rid < c) { m = mm; split = rid; break; }
        rid -= c;
    }
    const int b   = blockIdx.y;
    const int kt0 = split * TPB;
    const int kt1 = (kt0 + TPB < m + 1) ? (kt0 + TPB) : (m + 1);
    const long brow = (long)b * SEQ;
    const int rg = m * MT + w * 16 + g;    // global q row (low of pair)

    // Q fragments (persist across tiles)
    unsigned qh[4][4];
    {
        long base0 = (brow + rg) * 32;
        long base8 = base0 + 8 * 32;
        #pragma unroll
        for (int kk = 0; kk < 4; kk++) {
            int wlo = 8*kk + t4, whi = wlo + 4;
            qh[kk][0] = g_Qh[base0 + wlo]; qh[kk][1] = g_Qh[base8 + wlo];
            qh[kk][2] = g_Qh[base0 + whi]; qh[kk][3] = g_Qh[base8 + whi];
        }
    }

    float O[8][4];
    #pragma unroll
    for (int i = 0; i < 8; i++)
        #pragma unroll
        for (int j = 0; j < 4; j++) O[i][j] = 0.f;
    float lacc0 = 0.f, lacc1 = 0.f;

    // prologue: prefetch first tile into buffer 0
    attn_issue(sbase, 0, tid, b, brow, kt0);
    CPA_COMMIT();
    int cur = 0;

    for (int kt = kt0; kt < kt1; kt++) {
        CPA_WAIT0();
        __syncthreads();                 // current buffer ready; prev readers done
        if (kt + 1 < kt1) {
            attn_issue(sbase, (cur ^ 1) * BUF_W, tid, b, brow, kt + 1);
            CPA_COMMIT();
        }
        const unsigned* Khs = smw + cur * BUF_W + BK_OFF;
        const unsigned* Vhs = smw + cur * BUF_W + BV_OFF;

        // ---- S = Q K^T (16 n-tiles of 8 keys) ----
        float S[16][4];
        #pragma unroll
        for (int j = 0; j < 16; j++)
            #pragma unroll
            for (int r = 0; r < 4; r++) S[j][r] = 0.f;

        #pragma unroll
        for (int kk = 0; kk < 4; kk++) {
            #pragma unroll
            for (int j = 0; j < 16; j++) {
                const unsigned* kh = Khs + (j*8 + g)*36 + 8*kk + t4;
                MMAH(S[j], qh[kk], kh[0], kh[4]);
            }
        }

        // ---- softmax (no max-sub, MUFU ex2) + build P fp16 A-fragments ----
        const int diag = (kt == m);
        const int kbase = kt * KT;
        unsigned ph[8][4];
        #pragma unroll
        for (int j = 0; j < 16; j++) {
            float p0 = ex2(S[j][0] * SCALE_LOG2E);
            float p1 = ex2(S[j][1] * SCALE_LOG2E);
            float p2 = ex2(S[j][2] * SCALE_LOG2E);
            float p3 = ex2(S[j][3] * SCALE_LOG2E);
            if (diag) {
                int col = kbase + j*8 + 2*t4;
                if (col     > rg)     p0 = 0.f;
                if (col + 1 > rg)     p1 = 0.f;
                if (col     > rg + 8) p2 = 0.f;
                if (col + 1 > rg + 8) p3 = 0.f;
            }
            lacc0 += p0 + p1;
            lacc1 += p2 + p3;
            int kk2 = j >> 1, hf = (j & 1) * 2;
            ph[kk2][hf]     = packhf(p1, p0);
            ph[kk2][hf + 1] = packhf(p3, p2);
        }

        // ---- O += P V ----
        #pragma unroll
        for (int kk2 = 0; kk2 < 8; kk2++) {
            #pragma unroll
            for (int n2 = 0; n2 < 8; n2++) {
                const unsigned* vh = Vhs + (n2*8 + g)*68 + 8*kk2 + t4;
                MMAH(O[n2], ph[kk2], vh[0], vh[4]);
            }
        }
        cur ^= 1;
    }

    // ---- reduce l over quad, write partials ----
    lacc0 += __shfl_xor_sync(0xffffffffu, lacc0, 1);
    lacc0 += __shfl_xor_sync(0xffffffffu, lacc0, 2);
    lacc1 += __shfl_xor_sync(0xffffffffu, lacc1, 1);
    lacc1 += __shfl_xor_sync(0xffffffffu, lacc1, 2);

    const int pidx = (b * NMT + m) * MAXSPLIT + split;
    if (t4 == 0) {
        g_Lpart[pidx*128 + w*16 + g]     = lacc0;
        g_Lpart[pidx*128 + w*16 + g + 8] = lacc1;
    }
    float* op = g_Opart + ((size_t)pidx*128 + w*16 + g) * 64;
    #pragma unroll
    for (int n2 = 0; n2 < 8; n2++) {
        *(float2*)&op[n2*8 + 2*t4]          = make_float2(O[n2][0], O[n2][1]);
        *(float2*)&op[8*64 + n2*8 + 2*t4]   = make_float2(O[n2][2], O[n2][3]);
    }
}

// ---------------- combine split partials (float4, 2 independent chains) ----------------
__global__ void combine_kernel(float* __restrict__ out) {
    int idx4 = blockIdx.x * blockDim.x + threadIdx.x;
    if (idx4 >= BS * HD / 4) return;
    int row = idx4 >> 4, d4 = idx4 & 15;
    int b = row >> 12;
    int s_in_b = row & 4095;
    int m = s_in_b >> 7, r = s_in_b & 127;
    int nsp = (m + TPB) >> 3;
    int p0 = (b * NMT + m) * MAXSPLIT;

    float4 a0 = make_float4(0.f, 0.f, 0.f, 0.f);
    float4 a1 = make_float4(0.f, 0.f, 0.f, 0.f);
    float l0 = 0.f, l1 = 0.f;
    #pragma unroll 1
    for (int s = 0; s + 1 < nsp; s += 2) {
        int p = p0 + s;
        float4 v0 = *(const float4*)&g_Opart[((size_t)p * 128 + r) * 64 + d4*4];
        float4 v1 = *(const float4*)&g_Opart[((size_t)(p+1) * 128 + r) * 64 + d4*4];
        a0.x += v0.x; a0.y += v0.y; a0.z += v0.z; a0.w += v0.w;
        a1.x += v1.x; a1.y += v1.y; a1.z += v1.z; a1.w += v1.w;
        l0 += g_Lpart[p * 128 + r];
        l1 += g_Lpart[(p+1) * 128 + r];
    }
    if (nsp & 1) {
        int p = p0 + nsp - 1;
        float4 v = *(const float4*)&g_Opart[((size_t)p * 128 + r) * 64 + d4*4];
        a0.x += v.x; a0.y += v.y; a0.z += v.z; a0.w += v.w;
        l0 += g_Lpart[p * 128 + r];
    }
    float inv = 1.f / (l0 + l1);
    *(float4*)&out[idx4*4] = make_float4((a0.x + a1.x) * inv, (a0.y + a1.y) * inv,
                                         (a0.z + a1.z) * inv, (a0.w + a1.w) * inv);
}

extern "C" void kernel_launch(void* const* d_in, const int* in_sizes, int n_in,
                              void* d_out, int out_size) {
    const float* x  = (const float*)d_in[0];
    const float* WQ = (const float*)d_in[1];
    const float* WK = (const float*)d_in[2];
    const float* WV = (const float*)d_in[3];
    float* out = (float*)d_out;

    cudaFuncSetAttribute(qkv_mma,  cudaFuncAttributeMaxDynamicSharedMemorySize, QSMEM_BYTES);
    cudaFuncSetAttribute(attn_mma, cudaFuncAttributeMaxDynamicSharedMemorySize, SMEM_BYTES);

    wprep_kernel<<<192, 256>>>(WQ, WK, WV);
    qkv_mma<<<BS / 128, 256, QSMEM_BYTES>>>(x);
    attn_mma<<<dim3(BLKS_PER_B, BATCH), 256, SMEM_BYTES>>>();
    combine_kernel<<<(BS * HD / 4 + 255) / 256, 256>>>(out);
}

// round 9
// speedup vs baseline: 10.1058x; 1.1864x over previous
#include <cuda_runtime.h>
#include <cuda_fp16.h>
#include <math.h>
#include <stdint.h>

#define BATCH 4
#define SEQ   4096
#define EMB   512
#define HD    64
#define BS    (BATCH*SEQ)
#define MT    128
#define NMT   (SEQ/MT)            // 32
#define KT    128
#define TPB   8                   // max key tiles per block
#define BLKS_PER_B 80             // sum_m ceil((m+1)/8)
#define MAXSPLIT 4
#define SCALE_LOG2E 0.06375872036f   // log2(e)/sqrt(512)

// ---------------- device scratch ----------------
__device__ unsigned g_Qh[BS*32];                    // packed fp16 pairs, [row][32 words]
__device__ unsigned g_Kh[BS*32];
__device__ unsigned g_Vth[BATCH*64*2048];           // V^T packed key-pairs, [b*64+d][2048]
__device__ unsigned g_Wth[192*256];                 // W^T packed: [n(Q64|K64|V64)][256 kw]
__device__ float    g_Opart[(size_t)BATCH*NMT*MAXSPLIT*MT*HD];
__device__ float    g_Lpart[BATCH*NMT*MAXSPLIT*MT];

// pack two fp32 -> fp16x2 (first arg = odd/upper half, second = even/lower)
static __device__ __forceinline__ unsigned packhf(float o, float e) {
    unsigned r;
    asm("cvt.rn.f16x2.f32 %0, %1, %2;" : "=r"(r) : "f"(o), "f"(e));
    return r;
}
// fast exp2 via MUFU (guaranteed, independent of compile flags)
static __device__ __forceinline__ float ex2(float x) {
    float r;
    asm("ex2.approx.ftz.f32 %0, %1;" : "=f"(r) : "f"(x));
    return r;
}
static __device__ __forceinline__ uint32_t smem_u32(const void* p) {
    uint32_t a;
    asm("{ .reg .u64 t; cvta.to.shared.u64 t, %1; cvt.u32.u64 %0, t; }" : "=r"(a) : "l"(p));
    return a;
}
static __device__ __forceinline__ void cpa16(uint32_t s, const void* g) {
    asm volatile("cp.async.cg.shared.global [%0], [%1], 16;" :: "r"(s), "l"(g));
}
#define CPA_COMMIT() asm volatile("cp.async.commit_group;" ::: "memory")
#define CPA_WAIT0()  asm volatile("cp.async.wait_group 0;" ::: "memory")
#define CPA_WAIT1()  asm volatile("cp.async.wait_group 1;" ::: "memory")

#define MMAH(C, A, b0v, b1v)                                                     \
    asm volatile("mma.sync.aligned.m16n8k16.row.col.f32.f16.f16.f32 "            \
        "{%0,%1,%2,%3}, {%4,%5,%6,%7}, {%8,%9}, {%0,%1,%2,%3};"                  \
        : "+f"((C)[0]), "+f"((C)[1]), "+f"((C)[2]), "+f"((C)[3])                 \
        : "r"((A)[0]), "r"((A)[1]), "r"((A)[2]), "r"((A)[3]), "r"(b0v), "r"(b1v))

// ---------------- W^T prep: [n=192][k=512] -> packed fp16 [n][256 words] --------
__global__ void wprep_kernel(const float* __restrict__ WQ,
                             const float* __restrict__ WK,
                             const float* __restrict__ WV) {
    int n  = blockIdx.x;                 // 0..191
    int kp = threadIdx.x;                // 0..255 (key-dim pair)
    const float* W = (n < 64) ? WQ : (n < 128 ? WK : WV);
    int nc = n & 63;
    float v0 = W[(2*kp)     * 64 + nc];
    float v1 = W[(2*kp + 1) * 64 + nc];
    g_Wth[n*256 + kp] = packhf(v1, v0);
}

// ---------------- QKV projection via single-fp16 HMMA, double-buffered ----------------
// smem words: xh0 @0, xh1 @4608 (each 128*36=4608), wh0 @9216, wh1 @16128 (each 192*36=6912)
// total 23040 w = 92160 B.
#define QX0 0
#define QX1 4608
#define QW0 9216
#define QW1 16128
#define QSMEM_BYTES (23040*4)

__global__ __launch_bounds__(256, 1) void qkv_mma(const float* __restrict__ x) {
    extern __shared__ unsigned qs[];
    const uint32_t sbase = smem_u32(qs);

    const int tid  = threadIdx.x;
    const int w    = tid >> 5;
    const int lane = tid & 31;
    const int g    = lane >> 2;
    const int t4   = lane & 3;
    const long r0  = (long)blockIdx.x * 128;

    const int xr = tid >> 1, xhf = tid & 1;          // x conversion: row, half
    const int xo = xr*36 + xhf*16;

    float C[24][4];
    #pragma unroll
    for (int j = 0; j < 24; j++)
        #pragma unroll
        for (int i = 0; i < 4; i++) C[j][i] = 0.f;

    const int bg0 = (w*16 + g) * 36;
    const int bg8 = bg0 + 8*36;

    // W cp.async issue helper offsets
    const int wn  = tid >> 3, wc4 = tid & 7;         // covers 192 rows x 8 uint4 in 6 steps? 256 thr -> n=tid>>3 (0..31)

    // ---- prologue: x(0) regs + W(0) cp.async + STS x(0) ----
    float4 xv[8];
    {
        const float4* xp = (const float4*)&x[(r0 + xr) * EMB + 0 + xhf*32];
        #pragma unroll
        for (int i = 0; i < 8; i++) xv[i] = xp[i];
    }
    {
        uint32_t wb = sbase + QW0*4;
        #pragma unroll
        for (int i = 0; i < 6; i++) {
            int idx = tid + i*256;
            int n = idx >> 3, c4 = idx & 7;
            cpa16(wb + (n*36 + c4*4)*4, g_Wth + n*256 + 0 + c4*4);
        }
    }
    CPA_COMMIT();
    #pragma unroll
    for (int i = 0; i < 8; i++) {
        qs[QX0 + xo + i*2]     = packhf(xv[i].y, xv[i].x);
        qs[QX0 + xo + i*2 + 1] = packhf(xv[i].w, xv[i].z);
    }

    for (int it = 0; it < 8; it++) {
        const int cur = it & 1;
        const int xcur = cur ? QX1 : QX0;
        const int xnxt = cur ? QX0 : QX1;
        const int wcur = cur ? QW1 : QW0;
        const int wnxt = cur ? QW0 : QW1;

        if (it < 7) {
            const float4* xp = (const float4*)&x[(r0 + xr) * EMB + (it+1)*64 + xhf*32];
            #pragma unroll
            for (int i = 0; i < 8; i++) xv[i] = xp[i];
            uint32_t wb = sbase + wnxt*4;
            int kw0 = ((it+1)*64) >> 1;
            #pragma unroll
            for (int i = 0; i < 6; i++) {
                int idx = tid + i*256;
                int n = idx >> 3, c4 = idx & 7;
                cpa16(wb + (n*36 + c4*4)*4, g_Wth + n*256 + kw0 + c4*4);
            }
            CPA_COMMIT();
            CPA_WAIT1();
        } else {
            CPA_WAIT0();
        }
        __syncthreads();   // xh[cur]/wh[cur] ready; prev readers of [nxt] done

        const unsigned* xh = qs + xcur;
        const unsigned* wh = qs + wcur;
        #pragma unroll
        for (int kk = 0; kk < 4; kk++) {
            int wlo = 8*kk + t4, whi = wlo + 4;
            unsigned ah[4] = { xh[bg0+wlo], xh[bg8+wlo], xh[bg0+whi], xh[bg8+whi] };
            #pragma unroll
            for (int j = 0; j < 24; j++) {
                const unsigned* bp = wh + (j*8 + g)*36 + wlo;
                MMAH(C[j], ah, bp[0], bp[4]);
            }
        }

        if (it < 7) {
            #pragma unroll
            for (int i = 0; i < 8; i++) {
                qs[xnxt + xo + i*2]     = packhf(xv[i].y, xv[i].x);
                qs[xnxt + xo + i*2 + 1] = packhf(xv[i].w, xv[i].z);
            }
        }
        __syncthreads();
    }

    // ---- epilogue: Q (j 0..7), K (j 8..15) -> packed fp16 global ----
    const long rowg = r0 + w*16 + g;
    #pragma unroll
    for (int j = 0; j < 16; j++) {
        unsigned* oh = (j < 8) ? g_Qh : g_Kh;
        int wi = (j & 7)*4 + t4;
        oh[rowg*32 + wi]     = packhf(C[j][1], C[j][0]);
        oh[(rowg+8)*32 + wi] = packhf(C[j][3], C[j][2]);
    }

    // ---- V (j 16..23): stage fp32 in smem, transpose+pack to g_Vth ----
    float* vs = (float*)qs;   // [128][66] floats = 8448 w, fits in 23040 w
    #pragma unroll
    for (int j = 16; j < 24; j++) {
        int col = (j - 16)*8 + 2*t4;
        *(float2*)&vs[(w*16 + g)*66 + col]     = make_float2(C[j][0], C[j][1]);
        *(float2*)&vs[(w*16 + g + 8)*66 + col] = make_float2(C[j][2], C[j][3]);
    }
    __syncthreads();

    {
        int b   = (int)(r0 >> 12);
        int kpb = (int)(r0 & 4095) >> 1;   // keypair base within batch
        int kp  = tid & 63;
        int d0  = (tid >> 6) * 16;
        #pragma unroll
        for (int i = 0; i < 16; i++) {
            int d = d0 + i;
            float v0 = vs[(2*kp)*66 + d];
            float v1 = vs[(2*kp + 1)*66 + d];
            g_Vth[((size_t)(b*64 + d)) * 2048 + kpb + kp] = packhf(v1, v0);
        }
    }
}

// ---------------- fp16 HMMA flash attention, cp.async double-buffered, occ 2 ----------
// buffer (words): K[128][36]=4608, V[64][68]=4352 -> 8960/buffer; 2 buffers = 17920 w.
#define BUF_W   8960
#define BK_OFF  0
#define BV_OFF  4608
#define SMEM_BYTES (17920*4)

static __device__ __forceinline__ void attn_issue(uint32_t sbase, int bufw,
                                                  int tid, int b, long brow, int kt) {
    const uint4* KH = (const uint4*)g_Kh + (brow + (long)kt * KT) * 8;
    uint32_t kb = sbase + (bufw + BK_OFF) * 4;
    #pragma unroll
    for (int i = 0; i < 4; i++) {
        int idx = tid + i * 256;
        int r = idx >> 3, c4 = idx & 7;
        cpa16(kb + (r*36 + c4*4)*4, &KH[r*8 + c4]);
    }
    uint32_t vb = sbase + (bufw + BV_OFF) * 4;
    #pragma unroll
    for (int i = 0; i < 4; i++) {
        int idx = tid + i * 256;
        int d = idx >> 4, c4 = idx & 15;
        cpa16(vb + (d*68 + c4*4)*4,
              (const uint4*)g_Vth + ((size_t)(b*64 + d)) * 512 + (size_t)kt * 16 + c4);
    }
}

__global__ __launch_bounds__(256, 2) void attn_mma() {
    extern __shared__ unsigned smw[];
    const uint32_t sbase = smem_u32(smw);

    const int tid  = threadIdx.x;
    const int w    = tid >> 5;
    const int lane = tid & 31;
    const int g    = lane >> 2;
    const int t4   = lane & 3;

    // decode (m, split)
    int rid = blockIdx.x, m = 0, split = 0;
    #pragma unroll 1
    for (int mm = 0; mm < NMT; mm++) {
        int c = (mm + TPB) >> 3;
        if (rid < c) { m = mm; split = rid; break; }
        rid -= c;
    }
    const int b   = blockIdx.y;
    const int kt0 = split * TPB;
    const int kt1 = (kt0 + TPB < m + 1) ? (kt0 + TPB) : (m + 1);
    const long brow = (long)b * SEQ;
    const int rg = m * MT + w * 16 + g;    // global q row (low of pair)

    // Q fragments (persist across tiles)
    unsigned qh[4][4];
    {
        long base0 = (brow + rg) * 32;
        long base8 = base0 + 8 * 32;
        #pragma unroll
        for (int kk = 0; kk < 4; kk++) {
            int wlo = 8*kk + t4, whi = wlo + 4;
            qh[kk][0] = g_Qh[base0 + wlo]; qh[kk][1] = g_Qh[base8 + wlo];
            qh[kk][2] = g_Qh[base0 + whi]; qh[kk][3] = g_Qh[base8 + whi];
        }
    }

    float O[8][4];
    #pragma unroll
    for (int i = 0; i < 8; i++)
        #pragma unroll
        for (int j = 0; j < 4; j++) O[i][j] = 0.f;
    float lacc0 = 0.f, lacc1 = 0.f;

    // prologue: prefetch first tile into buffer 0
    attn_issue(sbase, 0, tid, b, brow, kt0);
    CPA_COMMIT();
    int cur = 0;

    for (int kt = kt0; kt < kt1; kt++) {
        CPA_WAIT0();
        __syncthreads();                 // current buffer ready; prev readers done
        if (kt + 1 < kt1) {
            attn_issue(sbase, (cur ^ 1) * BUF_W, tid, b, brow, kt + 1);
            CPA_COMMIT();
        }
        const unsigned* Khs = smw + cur * BUF_W + BK_OFF;
        const unsigned* Vhs = smw + cur * BUF_W + BV_OFF;

        const int diag = (kt == m);
        const int kbase = kt * KT;

        // two 64-key halves: halves the live register set (occ 2)
        #pragma unroll
        for (int h = 0; h < 2; h++) {
            float S[8][4];
            #pragma unroll
            for (int j = 0; j < 8; j++)
                #pragma unroll
                for (int r = 0; r < 4; r++) S[j][r] = 0.f;

            #pragma unroll
            for (int kk = 0; kk < 4; kk++) {
                #pragma unroll
                for (int j = 0; j < 8; j++) {
                    const unsigned* kh = Khs + ((h*8 + j)*8 + g)*36 + 8*kk + t4;
                    MMAH(S[j], qh[kk], kh[0], kh[4]);
                }
            }

            unsigned ph[4][4];
            #pragma unroll
            for (int j = 0; j < 8; j++) {
                float p0 = ex2(S[j][0] * SCALE_LOG2E);
                float p1 = ex2(S[j][1] * SCALE_LOG2E);
                float p2 = ex2(S[j][2] * SCALE_LOG2E);
                float p3 = ex2(S[j][3] * SCALE_LOG2E);
                if (diag) {
                    int col = kbase + (h*8 + j)*8 + 2*t4;
                    if (col     > rg)     p0 = 0.f;
                    if (col + 1 > rg)     p1 = 0.f;
                    if (col     > rg + 8) p2 = 0.f;
                    if (col + 1 > rg + 8) p3 = 0.f;
                }
                lacc0 += p0 + p1;
                lacc1 += p2 + p3;
                int kk2 = j >> 1, hf = (j & 1) * 2;
                ph[kk2][hf]     = packhf(p1, p0);
                ph[kk2][hf + 1] = packhf(p3, p2);
            }

            #pragma unroll
            for (int kk2 = 0; kk2 < 4; kk2++) {
                #pragma unroll
                for (int n2 = 0; n2 < 8; n2++) {
                    const unsigned* vh = Vhs + (n2*8 + g)*68 + 8*(h*4 + kk2) + t4;
                    MMAH(O[n2], ph[kk2], vh[0], vh[4]);
                }
            }
        }
        cur ^= 1;
    }

    // ---- reduce l over quad, write partials ----
    lacc0 += __shfl_xor_sync(0xffffffffu, lacc0, 1);
    lacc0 += __shfl_xor_sync(0xffffffffu, lacc0, 2);
    lacc1 += __shfl_xor_sync(0xffffffffu, lacc1, 1);
    lacc1 += __shfl_xor_sync(0xffffffffu, lacc1, 2);

    const int pidx = (b * NMT + m) * MAXSPLIT + split;
    if (t4 == 0) {
        g_Lpart[pidx*128 + w*16 + g]     = lacc0;
        g_Lpart[pidx*128 + w*16 + g + 8] = lacc1;
    }
    float* op = g_Opart + ((size_t)pidx*128 + w*16 + g) * 64;
    #pragma unroll
    for (int n2 = 0; n2 < 8; n2++) {
        *(float2*)&op[n2*8 + 2*t4]          = make_float2(O[n2][0], O[n2][1]);
        *(float2*)&op[8*64 + n2*8 + 2*t4]   = make_float2(O[n2][2], O[n2][3]);
    }
}

// ---------------- combine split partials (float4, 2 independent chains) ----------------
__global__ void combine_kernel(float* __restrict__ out) {
    int idx4 = blockIdx.x * blockDim.x + threadIdx.x;
    if (idx4 >= BS * HD / 4) return;
    int row = idx4 >> 4, d4 = idx4 & 15;
    int b = row >> 12;
    int s_in_b = row & 4095;
    int m = s_in_b >> 7, r = s_in_b & 127;
    int nsp = (m + TPB) >> 3;
    int p0 = (b * NMT + m) * MAXSPLIT;

    float4 a0 = make_float4(0.f, 0.f, 0.f, 0.f);
    float4 a1 = make_float4(0.f, 0.f, 0.f, 0.f);
    float l0 = 0.f, l1 = 0.f;
    #pragma unroll 1
    for (int s = 0; s + 1 < nsp; s += 2) {
        int p = p0 + s;
        float4 v0 = *(const float4*)&g_Opart[((size_t)p * 128 + r) * 64 + d4*4];
        float4 v1 = *(const float4*)&g_Opart[((size_t)(p+1) * 128 + r) * 64 + d4*4];
        a0.x += v0.x; a0.y += v0.y; a0.z += v0.z; a0.w += v0.w;
        a1.x += v1.x; a1.y += v1.y; a1.z += v1.z; a1.w += v1.w;
        l0 += g_Lpart[p * 128 + r];
        l1 += g_Lpart[(p+1) * 128 + r];
    }
    if (nsp & 1) {
        int p = p0 + nsp - 1;
        float4 v = *(const float4*)&g_Opart[((size_t)p * 128 + r) * 64 + d4*4];
        a0.x += v.x; a0.y += v.y; a0.z += v.z; a0.w += v.w;
        l0 += g_Lpart[p * 128 + r];
    }
    float inv = 1.f / (l0 + l1);
    *(float4*)&out[idx4*4] = make_float4((a0.x + a1.x) * inv, (a0.y + a1.y) * inv,
                                         (a0.z + a1.z) * inv, (a0.w + a1.w) * inv);
}

extern "C" void kernel_launch(void* const* d_in, const int* in_sizes, int n_in,
                              void* d_out, int out_size) {
    const float* x  = (const float*)d_in[0];
    const float* WQ = (const float*)d_in[1];
    const float* WK = (const float*)d_in[2];
    const float* WV = (const float*)d_in[3];
    float* out = (float*)d_out;

    cudaFuncSetAttribute(qkv_mma,  cudaFuncAttributeMaxDynamicSharedMemorySize, QSMEM_BYTES);
    cudaFuncSetAttribute(attn_mma, cudaFuncAttributeMaxDynamicSharedMemorySize, SMEM_BYTES);

    wprep_kernel<<<192, 256>>>(WQ, WK, WV);
    qkv_mma<<<BS / 128, 256, QSMEM_BYTES>>>(x);
    attn_mma<<<dim3(BLKS_PER_B, BATCH), 256, SMEM_BYTES>>>();
    combine_kernel<<<(BS * HD / 4 + 255) / 256, 256>>>(out);
}

// round 10
// speedup vs baseline: 10.9965x; 1.0881x over previous
#include <cuda_runtime.h>
#include <cuda_fp16.h>
#include <math.h>
#include <stdint.h>

#define BATCH 4
#define SEQ   4096
#define EMB   512
#define HD    64
#define BS    (BATCH*SEQ)
#define MT    128
#define NMT   (SEQ/MT)            // 32
#define KT    128
#define TPB   8                   // max key tiles per block
#define BLKS_PER_B 80             // sum_m ceil((m+1)/8)
#define MAXSPLIT 4
#define SCALE_LOG2E 0.06375872036f   // log2(e)/sqrt(512)

// ---------------- device scratch ----------------
__device__ unsigned g_Qh[BS*32];                    // packed fp16 pairs, [row][32 words]
__device__ unsigned g_Kh[BS*32];
__device__ unsigned g_Vth[BATCH*64*2048];           // V^T packed key-pairs, [b*64+d][2048]
__device__ unsigned g_Wth[192*256];                 // W^T packed: [n(Q64|K64|V64)][256 kw]
__device__ float    g_Opart[(size_t)BATCH*NMT*MAXSPLIT*MT*HD];
__device__ float    g_Lpart[BATCH*NMT*MAXSPLIT*MT];

static __device__ __forceinline__ unsigned packhf(float o, float e) {
    unsigned r;
    asm("cvt.rn.f16x2.f32 %0, %1, %2;" : "=r"(r) : "f"(o), "f"(e));
    return r;
}
static __device__ __forceinline__ float ex2(float x) {
    float r;
    asm("ex2.approx.ftz.f32 %0, %1;" : "=f"(r) : "f"(x));
    return r;
}
static __device__ __forceinline__ uint32_t smem_u32(const void* p) {
    uint32_t a;
    asm("{ .reg .u64 t; cvta.to.shared.u64 t, %1; cvt.u32.u64 %0, t; }" : "=r"(a) : "l"(p));
    return a;
}
static __device__ __forceinline__ void cpa16(uint32_t s, const void* g) {
    asm volatile("cp.async.cg.shared.global [%0], [%1], 16;" :: "r"(s), "l"(g));
}
#define CPA_COMMIT() asm volatile("cp.async.commit_group;" ::: "memory")
#define CPA_WAIT0()  asm volatile("cp.async.wait_group 0;" ::: "memory")
#define CPA_WAIT1()  asm volatile("cp.async.wait_group 1;" ::: "memory")

static __device__ __forceinline__ void ldsm4(unsigned &r0, unsigned &r1,
                                             unsigned &r2, unsigned &r3, uint32_t a) {
    asm volatile("ldmatrix.sync.aligned.m8n8.x4.shared.b16 {%0,%1,%2,%3}, [%4];"
                 : "=r"(r0), "=r"(r1), "=r"(r2), "=r"(r3) : "r"(a));
}

#define MMAH(C, A, b0v, b1v)                                                     \
    asm volatile("mma.sync.aligned.m16n8k16.row.col.f32.f16.f16.f32 "            \
        "{%0,%1,%2,%3}, {%4,%5,%6,%7}, {%8,%9}, {%0,%1,%2,%3};"                  \
        : "+f"((C)[0]), "+f"((C)[1]), "+f"((C)[2]), "+f"((C)[3])                 \
        : "r"((A)[0]), "r"((A)[1]), "r"((A)[2]), "r"((A)[3]), "r"(b0v), "r"(b1v))

// ---------------- W^T prep: [n=192][k=512] -> packed fp16 [n][256 words] --------
__global__ void wprep_kernel(const float* __restrict__ WQ,
                             const float* __restrict__ WK,
                             const float* __restrict__ WV) {
    int n  = blockIdx.x;                 // 0..191
    int kp = threadIdx.x;                // 0..255
    const float* W = (n < 64) ? WQ : (n < 128 ? WK : WV);
    int nc = n & 63;
    float v0 = W[(2*kp)     * 64 + nc];
    float v1 = W[(2*kp + 1) * 64 + nc];
    g_Wth[n*256 + kp] = packhf(v1, v0);
}

// ---------------- QKV projection via fp16 HMMA, double-buffered, ldmatrix --------
// smem words: xh0 @0, xh1 @4608 (128*36), wh0 @9216, wh1 @16128 (192*36). 23040 w.
#define QX0 0
#define QX1 4608
#define QW0 9216
#define QW1 16128
#define QSMEM_BYTES (23040*4)

__global__ __launch_bounds__(256, 1) void qkv_mma(const float* __restrict__ x) {
    extern __shared__ unsigned qs[];
    const uint32_t sbase = smem_u32(qs);

    const int tid  = threadIdx.x;
    const int w    = tid >> 5;
    const int lane = tid & 31;
    const int g    = lane >> 2;
    const int t4   = lane & 3;
    const long r0  = (long)blockIdx.x * 128;

    const int Lr = lane & 7, Lm = lane >> 3;
    const uint32_t aoff  = (uint32_t)(((w*16 + (Lm&1)*8 + Lr)*36 + (Lm>>1)*4) * 4);
    const uint32_t woffb = (uint32_t)((((Lm>>1)*8 + Lr)*36 + (Lm&1)*4) * 4);

    const int xr = tid >> 1, xhf = tid & 1;
    const int xo = xr*36 + xhf*16;

    float C[24][4];
    #pragma unroll
    for (int j = 0; j < 24; j++)
        #pragma unroll
        for (int i = 0; i < 4; i++) C[j][i] = 0.f;

    // ---- prologue: x(0) regs + W(0) cp.async + STS x(0) ----
    float4 xv[8];
    {
        const float4* xp = (const float4*)&x[(r0 + xr) * EMB + 0 + xhf*32];
        #pragma unroll
        for (int i = 0; i < 8; i++) xv[i] = xp[i];
    }
    {
        uint32_t wb = sbase + QW0*4;
        #pragma unroll
        for (int i = 0; i < 6; i++) {
            int idx = tid + i*256;
            int n = idx >> 3, c4 = idx & 7;
            cpa16(wb + (n*36 + c4*4)*4, g_Wth + n*256 + 0 + c4*4);
        }
    }
    CPA_COMMIT();
    #pragma unroll
    for (int i = 0; i < 8; i++) {
        qs[QX0 + xo + i*2]     = packhf(xv[i].y, xv[i].x);
        qs[QX0 + xo + i*2 + 1] = packhf(xv[i].w, xv[i].z);
    }

    for (int it = 0; it < 8; it++) {
        const int cur = it & 1;
        const int xcur = cur ? QX1 : QX0;
        const int xnxt = cur ? QX0 : QX1;
        const int wcur = cur ? QW1 : QW0;
        const int wnxt = cur ? QW0 : QW1;

        if (it < 7) {
            const float4* xp = (const float4*)&x[(r0 + xr) * EMB + (it+1)*64 + xhf*32];
            #pragma unroll
            for (int i = 0; i < 8; i++) xv[i] = xp[i];
            uint32_t wb = sbase + wnxt*4;
            int kw0 = ((it+1)*64) >> 1;
            #pragma unroll
            for (int i = 0; i < 6; i++) {
                int idx = tid + i*256;
                int n = idx >> 3, c4 = idx & 7;
                cpa16(wb + (n*36 + c4*4)*4, g_Wth + n*256 + kw0 + c4*4);
            }
            CPA_COMMIT();
            CPA_WAIT1();
        } else {
            CPA_WAIT0();
        }
        __syncthreads();   // cur buffers ready; prev readers of nxt done

        const uint32_t xb = sbase + xcur*4 + aoff;
        const uint32_t wb2 = sbase + wcur*4 + woffb;
        #pragma unroll
        for (int kk = 0; kk < 4; kk++) {
            unsigned ah[4];
            ldsm4(ah[0], ah[1], ah[2], ah[3], xb + kk*32);
            #pragma unroll
            for (int j2 = 0; j2 < 12; j2++) {
                unsigned b0, b1, b2, b3;
                ldsm4(b0, b1, b2, b3, wb2 + (uint32_t)((j2*2*288 + kk*8) * 4));
                MMAH(C[2*j2],   ah, b0, b1);
                MMAH(C[2*j2+1], ah, b2, b3);
            }
        }

        if (it < 7) {
            #pragma unroll
            for (int i = 0; i < 8; i++) {
                qs[xnxt + xo + i*2]     = packhf(xv[i].y, xv[i].x);
                qs[xnxt + xo + i*2 + 1] = packhf(xv[i].w, xv[i].z);
            }
        }
    }
    __syncthreads();

    // ---- epilogue: Q (j 0..7), K (j 8..15) -> packed fp16 global ----
    const long rowg = r0 + w*16 + g;
    #pragma unroll
    for (int j = 0; j < 16; j++) {
        unsigned* oh = (j < 8) ? g_Qh : g_Kh;
        int wi = (j & 7)*4 + t4;
        oh[rowg*32 + wi]     = packhf(C[j][1], C[j][0]);
        oh[(rowg+8)*32 + wi] = packhf(C[j][3], C[j][2]);
    }

    // ---- V (j 16..23): stage fp32 in smem, transpose+pack to g_Vth ----
    float* vs = (float*)qs;   // [128][66] floats = 8448 w
    #pragma unroll
    for (int j = 16; j < 24; j++) {
        int col = (j - 16)*8 + 2*t4;
        *(float2*)&vs[(w*16 + g)*66 + col]     = make_float2(C[j][0], C[j][1]);
        *(float2*)&vs[(w*16 + g + 8)*66 + col] = make_float2(C[j][2], C[j][3]);
    }
    __syncthreads();

    {
        int b   = (int)(r0 >> 12);
        int kpb = (int)(r0 & 4095) >> 1;
        int kp  = tid & 63;
        int d0  = (tid >> 6) * 16;
        #pragma unroll
        for (int i = 0; i < 16; i++) {
            int d = d0 + i;
            float v0 = vs[(2*kp)*66 + d];
            float v1 = vs[(2*kp + 1)*66 + d];
            g_Vth[((size_t)(b*64 + d)) * 2048 + kpb + kp] = packhf(v1, v0);
        }
    }
}

// ---------------- fp16 HMMA flash attention, cp.async dbl-buffered, occ2, ldmatrix ----
#define BUF_W   8960
#define BK_OFF  0
#define BV_OFF  4608
#define SMEM_BYTES (17920*4)

static __device__ __forceinline__ void attn_issue(uint32_t sbase, int bufw,
                                                  int tid, int b, long brow, int kt) {
    const uint4* KH = (const uint4*)g_Kh + (brow + (long)kt * KT) * 8;
    uint32_t kb = sbase + (bufw + BK_OFF) * 4;
    #pragma unroll
    for (int i = 0; i < 4; i++) {
        int idx = tid + i * 256;
        int r = idx >> 3, c4 = idx & 7;
        cpa16(kb + (r*36 + c4*4)*4, &KH[r*8 + c4]);
    }
    uint32_t vb = sbase + (bufw + BV_OFF) * 4;
    #pragma unroll
    for (int i = 0; i < 4; i++) {
        int idx = tid + i * 256;
        int d = idx >> 4, c4 = idx & 15;
        cpa16(vb + (d*68 + c4*4)*4,
              (const uint4*)g_Vth + ((size_t)(b*64 + d)) * 512 + (size_t)kt * 16 + c4);
    }
}

__global__ __launch_bounds__(256, 2) void attn_mma() {
    extern __shared__ unsigned smw[];
    const uint32_t sbase = smem_u32(smw);

    const int tid  = threadIdx.x;
    const int w    = tid >> 5;
    const int lane = tid & 31;
    const int g    = lane >> 2;
    const int t4   = lane & 3;

    const int Lr = lane & 7, Lm = lane >> 3;
    const uint32_t koff = (uint32_t)((((Lm>>1)*8 + Lr)*36 + (Lm&1)*4) * 4);
    const uint32_t voff = (uint32_t)((((Lm>>1)*8 + Lr)*68 + (Lm&1)*4) * 4);

    // decode (m, split); longest CTAs first (low blockIdx -> largest m)
    int rid = (BLKS_PER_B - 1) - (int)blockIdx.x, m = 0, split = 0;
    #pragma unroll 1
    for (int mm = 0; mm < NMT; mm++) {
        int c = (mm + TPB) >> 3;
        if (rid < c) { m = mm; split = rid; break; }
        rid -= c;
    }
    const int b   = blockIdx.y;
    const int kt0 = split * TPB;
    const int kt1 = (kt0 + TPB < m + 1) ? (kt0 + TPB) : (m + 1);
    const long brow = (long)b * SEQ;
    const int rg = m * MT + w * 16 + g;

    // Q fragments (persist across tiles)
    unsigned qh[4][4];
    {
        long base0 = (brow + rg) * 32;
        long base8 = base0 + 8 * 32;
        #pragma unroll
        for (int kk = 0; kk < 4; kk++) {
            int wlo = 8*kk + t4, whi = wlo + 4;
            qh[kk][0] = g_Qh[base0 + wlo]; qh[kk][1] = g_Qh[base8 + wlo];
            qh[kk][2] = g_Qh[base0 + whi]; qh[kk][3] = g_Qh[base8 + whi];
        }
    }

    float O[8][4];
    #pragma unroll
    for (int i = 0; i < 8; i++)
        #pragma unroll
        for (int j = 0; j < 4; j++) O[i][j] = 0.f;
    float lacc0 = 0.f, lacc1 = 0.f;

    attn_issue(sbase, 0, tid, b, brow, kt0);
    CPA_COMMIT();
    int cur = 0;

    for (int kt = kt0; kt < kt1; kt++) {
        CPA_WAIT0();
        __syncthreads();
        if (kt + 1 < kt1) {
            attn_issue(sbase, (cur ^ 1) * BUF_W, tid, b, brow, kt + 1);
            CPA_COMMIT();
        }
        const uint32_t kbb = sbase + (cur * BUF_W + BK_OFF) * 4 + koff;
        const uint32_t vbb = sbase + (cur * BUF_W + BV_OFF) * 4 + voff;

        const int diag = (kt == m);
        const int kbase = kt * KT;

        #pragma unroll
        for (int h = 0; h < 2; h++) {
            float S[8][4];
            #pragma unroll
            for (int j = 0; j < 8; j++)
                #pragma unroll
                for (int r = 0; r < 4; r++) S[j][r] = 0.f;

            #pragma unroll
            for (int kk = 0; kk < 4; kk++) {
                #pragma unroll
                for (int j2 = 0; j2 < 4; j2++) {
                    unsigned b0, b1, b2, b3;
                    ldsm4(b0, b1, b2, b3,
                          kbb + (uint32_t)(((h*8 + j2*2)*288 + kk*8) * 4));
                    MMAH(S[2*j2],   qh[kk], b0, b1);
                    MMAH(S[2*j2+1], qh[kk], b2, b3);
                }
            }

            unsigned ph[4][4];
            #pragma unroll
            for (int j = 0; j < 8; j++) {
                float p0 = ex2(S[j][0] * SCALE_LOG2E);
                float p1 = ex2(S[j][1] * SCALE_LOG2E);
                float p2 = ex2(S[j][2] * SCALE_LOG2E);
                float p3 = ex2(S[j][3] * SCALE_LOG2E);
                if (diag) {
                    int col = kbase + (h*8 + j)*8 + 2*t4;
                    if (col     > rg)     p0 = 0.f;
                    if (col + 1 > rg)     p1 = 0.f;
                    if (col     > rg + 8) p2 = 0.f;
                    if (col + 1 > rg + 8) p3 = 0.f;
                }
                lacc0 += p0 + p1;
                lacc1 += p2 + p3;
                int kk2 = j >> 1, hf = (j & 1) * 2;
                ph[kk2][hf]     = packhf(p1, p0);
                ph[kk2][hf + 1] = packhf(p3, p2);
            }

            #pragma unroll
            for (int kk2 = 0; kk2 < 4; kk2++) {
                #pragma unroll
                for (int n2p = 0; n2p < 4; n2p++) {
                    unsigned b0, b1, b2, b3;
                    ldsm4(b0, b1, b2, b3,
                          vbb + (uint32_t)((n2p*2*544 + (h*4 + kk2)*8) * 4));
                    MMAH(O[2*n2p],   ph[kk2], b0, b1);
                    MMAH(O[2*n2p+1], ph[kk2], b2, b3);
                }
            }
        }
        cur ^= 1;
    }

    // ---- reduce l over quad, write partials ----
    lacc0 += __shfl_xor_sync(0xffffffffu, lacc0, 1);
    lacc0 += __shfl_xor_sync(0xffffffffu, lacc0, 2);
    lacc1 += __shfl_xor_sync(0xffffffffu, lacc1, 1);
    lacc1 += __shfl_xor_sync(0xffffffffu, lacc1, 2);

    const int pidx = (b * NMT + m) * MAXSPLIT + split;
    if (t4 == 0) {
        g_Lpart[pidx*128 + w*16 + g]     = lacc0;
        g_Lpart[pidx*128 + w*16 + g + 8] = lacc1;
    }
    float* op = g_Opart + ((size_t)pidx*128 + w*16 + g) * 64;
    #pragma unroll
    for (int n2 = 0; n2 < 8; n2++) {
        *(float2*)&op[n2*8 + 2*t4]          = make_float2(O[n2][0], O[n2][1]);
        *(float2*)&op[8*64 + n2*8 + 2*t4]   = make_float2(O[n2][2], O[n2][3]);
    }
}

// ---------------- combine split partials (4 independent chains) ----------------
__global__ void combine_kernel(float* __restrict__ out) {
    int idx4 = blockIdx.x * blockDim.x + threadIdx.x;
    if (idx4 >= BS * HD / 4) return;
    int row = idx4 >> 4, d4 = idx4 & 15;
    int b = row >> 12;
    int s_in_b = row & 4095;
    int m = s_in_b >> 7, r = s_in_b & 127;
    int nsp = (m + TPB) >> 3;
    int p0 = (b * NMT + m) * MAXSPLIT;

    float4 a[4];
    float l[4];
    #pragma unroll
    for (int s = 0; s < 4; s++) {
        a[s] = make_float4(0.f, 0.f, 0.f, 0.f);
        l[s] = 0.f;
        if (s < nsp) {
            int p = p0 + s;
            a[s] = *(const float4*)&g_Opart[((size_t)p * 128 + r) * 64 + d4*4];
            l[s] = g_Lpart[p * 128 + r];
        }
    }
    float inv = 1.f / (l[0] + l[1] + l[2] + l[3]);
    *(float4*)&out[idx4*4] = make_float4((a[0].x + a[1].x + a[2].x + a[3].x) * inv,
                                         (a[0].y + a[1].y + a[2].y + a[3].y) * inv,
                                         (a[0].z + a[1].z + a[2].z + a[3].z) * inv,
                                         (a[0].w + a[1].w + a[2].w + a[3].w) * inv);
}

extern "C" void kernel_launch(void* const* d_in, const int* in_sizes, int n_in,
                              void* d_out, int out_size) {
    const float* x  = (const float*)d_in[0];
    const float* WQ = (const float*)d_in[1];
    const float* WK = (const float*)d_in[2];
    const float* WV = (const float*)d_in[3];
    float* out = (float*)d_out;

    cudaFuncSetAttribute(qkv_mma,  cudaFuncAttributeMaxDynamicSharedMemorySize, QSMEM_BYTES);
    cudaFuncSetAttribute(attn_mma, cudaFuncAttributeMaxDynamicSharedMemorySize, SMEM_BYTES);

    wprep_kernel<<<192, 256>>>(WQ, WK, WV);
    qkv_mma<<<BS / 128, 256, QSMEM_BYTES>>>(x);
    attn_mma<<<dim3(BLKS_PER_B, BATCH), 256, SMEM_BYTES>>>();
    combine_kernel<<<(BS * HD / 4 + 255) / 256, 256>>>(out);
}